// round 8
// baseline (speedup 1.0000x reference)
#include <cuda_runtime.h>
#include <math.h>

#define BATCH 8
#define SEQ   2048
#define EMB   512
#define DD1   1536
#define RDIM  512
#define MROWS (BATCH*SEQ)      // 16384
#define GAMMA_F 0.99f

// ---- device-global scratch (no allocations allowed) ----
__device__ float g_u[MROWS*DD1];      // silu(x@Wu+bu)           (M, D1)
__device__ float g_vbuf[MROWS*DD1];   // silu(x@Wv+bv)           (M, D1)
__device__ float g_vT[MROWS*DD1];     // v transposed            (B, D1, N)
__device__ float g_conv[MROWS*DD1];   // conv result             (M, D1)
__device__ float g_h[SEQ*RDIM];       // rpe hidden
__device__ float g_s[SEQ*RDIM];       // relu(srms(h))
__device__ float g_coeffs[SEQ*DD1];   // rpe output              (N, D1)
__device__ float g_acoefT[DD1*SEQ];   // decayed coeffs, transposed (D1, N)

// ---------------- RPE init: h[n,r] = n*Win[r] + bin[r] ----------------
__global__ void rpe_init_kernel(const float* __restrict__ Win,
                                const float* __restrict__ bin,
                                float* __restrict__ h) {
    int g = blockIdx.x * blockDim.x + threadIdx.x;
    if (g >= SEQ * RDIM) return;
    int n = g >> 9;          // /512
    int r = g & 511;
    h[g] = (float)n * Win[r] + bin[r];
}

// --------- srms + relu over rows of width 512 (one block per row) ---------
__global__ void srms_relu_kernel(const float* __restrict__ in,
                                 float* __restrict__ out) {
    int row = blockIdx.x;
    const float* p = in + (size_t)row * RDIM;
    int tid = threadIdx.x;                 // 256 threads
    float v0 = p[tid], v1 = p[tid + 256];
    float ss = v0 * v0 + v1 * v1;
    #pragma unroll
    for (int o = 16; o > 0; o >>= 1) ss += __shfl_xor_sync(0xffffffffu, ss, o);
    __shared__ float ws[8];
    if ((tid & 31) == 0) ws[tid >> 5] = ss;
    __syncthreads();
    float tot = 0.f;
    #pragma unroll
    for (int i = 0; i < 8; ++i) tot += ws[i];
    float scale = 1.f / (sqrtf(tot * (1.f / (float)RDIM)) + 1e-6f);
    out[(size_t)row * RDIM + tid]       = fmaxf(v0 * scale, 0.f);
    out[(size_t)row * RDIM + tid + 256] = fmaxf(v1 * scale, 0.f);
}

// ---------------- SGEMM: C = act((A [* A2]) @ B + bias) ----------------
// BM=BN=128, BK=8, 256 threads, 8x8 per thread. Requires M%128==0, N%128==0, K%8==0.
template<int ACT, int FUSE>
__global__ __launch_bounds__(256)
void sgemm_kernel(const float* __restrict__ A, const float* __restrict__ A2,
                  const float* __restrict__ B, const float* __restrict__ bias,
                  float* __restrict__ C, int M, int N, int K) {
    __shared__ __align__(16) float As[8][132];   // padded to dodge store conflicts
    __shared__ __align__(16) float Bs[8][128];

    int tid = threadIdx.x;
    int tx = tid & 15;        // col group
    int ty = tid >> 4;        // row group
    int row0 = blockIdx.y * 128;
    int col0 = blockIdx.x * 128;

    int a_row = tid >> 1;             // 0..127
    int a_col = (tid & 1) << 2;       // 0 or 4
    int b_row = tid >> 5;             // 0..7
    int b_col = (tid & 31) << 2;      // 0..124

    const float* Aptr  = A + (size_t)(row0 + a_row) * K + a_col;
    const float* A2ptr = FUSE ? (A2 + (size_t)(row0 + a_row) * K + a_col) : A;
    const float* Bptr  = B + (size_t)b_row * N + col0 + b_col;

    float acc[8][8];
    #pragma unroll
    for (int i = 0; i < 8; ++i)
        #pragma unroll
        for (int j = 0; j < 8; ++j) acc[i][j] = 0.f;

    int nk = K >> 3;
    for (int kt = 0; kt < nk; ++kt) {
        float4 av = *(const float4*)Aptr;
        if (FUSE) {
            float4 a2 = *(const float4*)A2ptr;
            av.x *= a2.x; av.y *= a2.y; av.z *= a2.z; av.w *= a2.w;
        }
        float4 bvv = *(const float4*)Bptr;
        As[a_col + 0][a_row] = av.x;
        As[a_col + 1][a_row] = av.y;
        As[a_col + 2][a_row] = av.z;
        As[a_col + 3][a_row] = av.w;
        *(float4*)&Bs[b_row][b_col] = bvv;
        __syncthreads();
        #pragma unroll
        for (int k = 0; k < 8; ++k) {
            float af[8], bf[8];
            #pragma unroll
            for (int i = 0; i < 8; ++i) af[i] = As[k][ty * 8 + i];
            #pragma unroll
            for (int j = 0; j < 8; ++j) bf[j] = Bs[k][tx * 8 + j];
            #pragma unroll
            for (int i = 0; i < 8; ++i)
                #pragma unroll
                for (int j = 0; j < 8; ++j)
                    acc[i][j] += af[i] * bf[j];
        }
        __syncthreads();
        Aptr += 8;
        if (FUSE) A2ptr += 8;
        Bptr += (size_t)8 * N;
    }

    #pragma unroll
    for (int i = 0; i < 8; ++i) {
        int r = row0 + ty * 8 + i;
        #pragma unroll
        for (int j = 0; j < 8; j += 4) {
            float4 o;
            float* op = &o.x;
            #pragma unroll
            for (int q = 0; q < 4; ++q) {
                float vv = acc[i][j + q] + bias[col0 + tx * 8 + j + q];
                if (ACT) vv = vv / (1.f + expf(-vv));   // silu
                op[q] = vv;
            }
            *(float4*)(C + (size_t)r * N + col0 + tx * 8 + j) = o;
        }
    }
}

// ---- scale by gamma^t and transpose coeffs (N,D1) -> (D1,N) ----
__global__ void coeff_scale_transpose(const float* __restrict__ coeffs,
                                      float* __restrict__ aT) {
    int g = blockIdx.x * blockDim.x + threadIdx.x;
    if (g >= SEQ * DD1) return;
    int t = g / DD1;
    int c = g - t * DD1;
    float dec = (t == 0) ? 1.f : powf(GAMMA_F, (float)t);
    aT[(size_t)c * SEQ + t] = coeffs[g] * dec;
}

// ---- transpose v: (B,N,D1) -> (B,D1,N), 32x32 smem tiles ----
__global__ void transpose_v_kernel(const float* __restrict__ v,
                                   float* __restrict__ vT) {
    __shared__ float tile[32][33];
    int b  = blockIdx.z;
    int n0 = blockIdx.x << 5;
    int c0 = blockIdx.y << 5;
    int tx = threadIdx.x, ty = threadIdx.y;   // (32,8)
    #pragma unroll
    for (int i = 0; i < 32; i += 8)
        tile[ty + i][tx] = v[((size_t)(b * SEQ + n0 + ty + i)) * DD1 + c0 + tx];
    __syncthreads();
    #pragma unroll
    for (int i = 0; i < 32; i += 8)
        vT[((size_t)(b * DD1 + c0 + ty + i)) * SEQ + n0 + tx] = tile[tx][ty + i];
}

// ---------------- causal per-channel convolution ----------------
// block = (n-tile of 512, one channel c), 128 threads.
// Each thread: 4 n's (tid + 128j) x 8 batches = 32 accumulators.
// out[b,n,c] = sum_{s<=n} a[c, n-s] * v[b,s,c]
__global__ __launch_bounds__(128)
void conv_kernel(const float* __restrict__ vT,     // (B, D1, N)
                 const float* __restrict__ aT,     // (D1, N), decayed
                 float* __restrict__ conv) {       // (B*N, D1)
    int c  = blockIdx.y;
    int n0 = blockIdx.x << 9;    // *512
    int tid = threadIdx.x;

    __shared__ __align__(16) float sv[BATCH][128];
    __shared__ float aw[640];

    float acc[4][8];
    #pragma unroll
    for (int j = 0; j < 4; ++j)
        #pragma unroll
        for (int b = 0; b < 8; ++b) acc[j][b] = 0.f;

    const float* ac = aT + (size_t)c * SEQ;
    int ntiles = (n0 + 512) >> 7;

    for (int st = 0; st < ntiles; ++st) {
        int s0 = st << 7;
        // coalesced fills
        #pragma unroll
        for (int b = 0; b < 8; ++b)
            sv[b][tid] = vT[((size_t)(b * DD1 + c)) * SEQ + s0 + tid];
        int t0 = n0 - s0 - 127;                  // aw[k] = a[t0+k], 0 if t<0
        #pragma unroll
        for (int j = 0; j < 5; ++j) {
            int k = tid + (j << 7);
            int t = t0 + k;
            aw[k] = (t >= 0 && t < SEQ) ? ac[t] : 0.f;
        }
        __syncthreads();

        #pragma unroll 4
        for (int ds = 0; ds < 128; ds += 4) {
            float4 vv[8];
            #pragma unroll
            for (int b = 0; b < 8; ++b) vv[b] = *(const float4*)&sv[b][ds];
            #pragma unroll
            for (int j = 0; j < 4; ++j) {
                int kb = tid + (j << 7) + 127 - ds;   // a index for s = s0+ds
                float a0 = aw[kb], a1 = aw[kb - 1], a2 = aw[kb - 2], a3 = aw[kb - 3];
                #pragma unroll
                for (int b = 0; b < 8; ++b)
                    acc[j][b] += a0 * vv[b].x + a1 * vv[b].y + a2 * vv[b].z + a3 * vv[b].w;
            }
        }
        __syncthreads();
    }

    #pragma unroll
    for (int j = 0; j < 4; ++j) {
        int n = n0 + tid + (j << 7);
        #pragma unroll
        for (int b = 0; b < 8; ++b)
            conv[((size_t)(b * SEQ + n)) * DD1 + c] = acc[j][b];
    }
}

// ================================================================
extern "C" void kernel_launch(void* const* d_in, const int* in_sizes, int n_in,
                              void* d_out, int out_size) {
    const float* x     = (const float*)d_in[0];
    const float* Wu    = (const float*)d_in[1];
    const float* bu    = (const float*)d_in[2];
    const float* Wv    = (const float*)d_in[3];
    const float* bv    = (const float*)d_in[4];
    const float* Wo    = (const float*)d_in[5];
    const float* bo    = (const float*)d_in[6];
    const float* rWin  = (const float*)d_in[7];
    const float* rbin  = (const float*)d_in[8];
    const float* rW    = (const float*)d_in[9];
    const float* rb    = (const float*)d_in[10];
    const float* rWout = (const float*)d_in[11];
    const float* rbout = (const float*)d_in[12];
    float* out = (float*)d_out;

    float *u, *v, *vT, *cv, *h, *s, *cf, *aT;
    cudaGetSymbolAddress((void**)&u,  g_u);
    cudaGetSymbolAddress((void**)&v,  g_vbuf);
    cudaGetSymbolAddress((void**)&vT, g_vT);
    cudaGetSymbolAddress((void**)&cv, g_conv);
    cudaGetSymbolAddress((void**)&h,  g_h);
    cudaGetSymbolAddress((void**)&s,  g_s);
    cudaGetSymbolAddress((void**)&cf, g_coeffs);
    cudaGetSymbolAddress((void**)&aT, g_acoefT);

    // ---- RPE MLP (tiny) ----
    rpe_init_kernel<<<(SEQ * RDIM + 255) / 256, 256>>>(rWin, rbin, h);
    for (int i = 0; i < 3; ++i) {
        srms_relu_kernel<<<SEQ, 256>>>(h, s);
        sgemm_kernel<0, 0><<<dim3(RDIM / 128, SEQ / 128), 256>>>(
            s, nullptr, rW + (size_t)i * RDIM * RDIM, rb + i * RDIM, h,
            SEQ, RDIM, RDIM);
    }
    srms_relu_kernel<<<SEQ, 256>>>(h, s);
    sgemm_kernel<0, 0><<<dim3(DD1 / 128, SEQ / 128), 256>>>(
        s, nullptr, rWout, rbout, cf, SEQ, DD1, RDIM);
    coeff_scale_transpose<<<(SEQ * DD1 + 255) / 256, 256>>>(cf, aT);

    // ---- u, v projections with silu ----
    sgemm_kernel<1, 0><<<dim3(DD1 / 128, MROWS / 128), 256>>>(
        x, nullptr, Wu, bu, u, MROWS, DD1, EMB);
    sgemm_kernel<1, 0><<<dim3(DD1 / 128, MROWS / 128), 256>>>(
        x, nullptr, Wv, bv, v, MROWS, DD1, EMB);

    // ---- causal conv ----
    transpose_v_kernel<<<dim3(SEQ / 32, DD1 / 32, BATCH), dim3(32, 8)>>>(v, vT);
    conv_kernel<<<dim3(SEQ / 512, DD1), 128>>>(vT, aT, cv);

    // ---- gated output GEMM: out = (u .* conv) @ Wo + bo ----
    sgemm_kernel<0, 1><<<dim3(EMB / 128, MROWS / 128), 256>>>(
        u, cv, Wo, bo, out, MROWS, EMB, DD1);
}

// round 9
// speedup vs baseline: 1.0037x; 1.0037x over previous
#include <cuda_runtime.h>
#include <math.h>

#define BATCH 8
#define SEQ   2048
#define EMB   512
#define DD1   1536
#define RDIM  512
#define MROWS (BATCH*SEQ)      // 16384
#define GAMMA_F 0.99f

// ---- device-global scratch (no allocations allowed) ----
__device__ float g_u[MROWS*DD1];      // silu(x@Wu+bu)           (M, D1)
__device__ float g_vbuf[MROWS*DD1];   // silu(x@Wv+bv)           (M, D1)
__device__ float g_vT[MROWS*DD1];     // v transposed            (B, D1, N)
__device__ float g_conv[MROWS*DD1];   // conv result             (M, D1)
__device__ float g_h[SEQ*RDIM];       // rpe hidden
__device__ float g_s[SEQ*RDIM];       // relu(srms(h))
__device__ float g_coeffs[SEQ*DD1];   // rpe output              (N, D1)
__device__ float g_acoefT[DD1*SEQ];   // decayed coeffs, transposed (D1, N)

// ---------------- RPE init: h[n,r] = n*Win[r] + bin[r] ----------------
__global__ void rpe_init_kernel(const float* __restrict__ Win,
                                const float* __restrict__ bin,
                                float* __restrict__ h) {
    int g = blockIdx.x * blockDim.x + threadIdx.x;
    if (g >= SEQ * RDIM) return;
    int n = g >> 9;          // /512
    int r = g & 511;
    h[g] = (float)n * Win[r] + bin[r];
}

// --------- srms + relu over rows of width 512 (one block per row) ---------
__global__ void srms_relu_kernel(const float* __restrict__ in,
                                 float* __restrict__ out) {
    int row = blockIdx.x;
    const float* p = in + (size_t)row * RDIM;
    int tid = threadIdx.x;                 // 256 threads
    float v0 = p[tid], v1 = p[tid + 256];
    float ss = v0 * v0 + v1 * v1;
    #pragma unroll
    for (int o = 16; o > 0; o >>= 1) ss += __shfl_xor_sync(0xffffffffu, ss, o);
    __shared__ float ws[8];
    if ((tid & 31) == 0) ws[tid >> 5] = ss;
    __syncthreads();
    float tot = 0.f;
    #pragma unroll
    for (int i = 0; i < 8; ++i) tot += ws[i];
    float scale = 1.f / (sqrtf(tot * (1.f / (float)RDIM)) + 1e-6f);
    out[(size_t)row * RDIM + tid]       = fmaxf(v0 * scale, 0.f);
    out[(size_t)row * RDIM + tid + 256] = fmaxf(v1 * scale, 0.f);
}

// ---------------- SGEMM: C = act((A [* A2]) @ B + bias) ----------------
// BM=BN=128, BK=8, 256 threads, 8x8 per thread. Requires M%128==0, N%128==0, K%8==0.
template<int ACT, int FUSE>
__global__ __launch_bounds__(256)
void sgemm_kernel(const float* __restrict__ A, const float* __restrict__ A2,
                  const float* __restrict__ B, const float* __restrict__ bias,
                  float* __restrict__ C, int M, int N, int K) {
    __shared__ __align__(16) float As[8][132];   // padded to dodge store conflicts
    __shared__ __align__(16) float Bs[8][128];

    int tid = threadIdx.x;
    int tx = tid & 15;        // col group
    int ty = tid >> 4;        // row group
    int row0 = blockIdx.y * 128;
    int col0 = blockIdx.x * 128;

    int a_row = tid >> 1;             // 0..127
    int a_col = (tid & 1) << 2;       // 0 or 4
    int b_row = tid >> 5;             // 0..7
    int b_col = (tid & 31) << 2;      // 0..124

    const float* Aptr  = A + (size_t)(row0 + a_row) * K + a_col;
    const float* A2ptr = FUSE ? (A2 + (size_t)(row0 + a_row) * K + a_col) : A;
    const float* Bptr  = B + (size_t)b_row * N + col0 + b_col;

    float acc[8][8];
    #pragma unroll
    for (int i = 0; i < 8; ++i)
        #pragma unroll
        for (int j = 0; j < 8; ++j) acc[i][j] = 0.f;

    int nk = K >> 3;
    for (int kt = 0; kt < nk; ++kt) {
        float4 av = *(const float4*)Aptr;
        if (FUSE) {
            float4 a2 = *(const float4*)A2ptr;
            av.x *= a2.x; av.y *= a2.y; av.z *= a2.z; av.w *= a2.w;
        }
        float4 bvv = *(const float4*)Bptr;
        As[a_col + 0][a_row] = av.x;
        As[a_col + 1][a_row] = av.y;
        As[a_col + 2][a_row] = av.z;
        As[a_col + 3][a_row] = av.w;
        *(float4*)&Bs[b_row][b_col] = bvv;
        __syncthreads();
        #pragma unroll
        for (int k = 0; k < 8; ++k) {
            float af[8], bf[8];
            #pragma unroll
            for (int i = 0; i < 8; ++i) af[i] = As[k][ty * 8 + i];
            #pragma unroll
            for (int j = 0; j < 8; ++j) bf[j] = Bs[k][tx * 8 + j];
            #pragma unroll
            for (int i = 0; i < 8; ++i)
                #pragma unroll
                for (int j = 0; j < 8; ++j)
                    acc[i][j] += af[i] * bf[j];
        }
        __syncthreads();
        Aptr += 8;
        if (FUSE) A2ptr += 8;
        Bptr += (size_t)8 * N;
    }

    #pragma unroll
    for (int i = 0; i < 8; ++i) {
        int r = row0 + ty * 8 + i;
        #pragma unroll
        for (int j = 0; j < 8; j += 4) {
            float4 o;
            float* op = &o.x;
            #pragma unroll
            for (int q = 0; q < 4; ++q) {
                float vv = acc[i][j + q] + bias[col0 + tx * 8 + j + q];
                if (ACT) vv = vv / (1.f + expf(-vv));   // silu
                op[q] = vv;
            }
            *(float4*)(C + (size_t)r * N + col0 + tx * 8 + j) = o;
        }
    }
}

// ---- scale by gamma^t and transpose coeffs (N,D1) -> (D1,N) ----
__global__ void coeff_scale_transpose(const float* __restrict__ coeffs,
                                      float* __restrict__ aT) {
    int g = blockIdx.x * blockDim.x + threadIdx.x;
    if (g >= SEQ * DD1) return;
    int t = g / DD1;
    int c = g - t * DD1;
    float dec = (t == 0) ? 1.f : powf(GAMMA_F, (float)t);
    aT[(size_t)c * SEQ + t] = coeffs[g] * dec;
}

// ---- transpose v: (B,N,D1) -> (B,D1,N), 32x32 smem tiles ----
__global__ void transpose_v_kernel(const float* __restrict__ v,
                                   float* __restrict__ vT) {
    __shared__ float tile[32][33];
    int b  = blockIdx.z;
    int n0 = blockIdx.x << 5;
    int c0 = blockIdx.y << 5;
    int tx = threadIdx.x, ty = threadIdx.y;   // (32,8)
    #pragma unroll
    for (int i = 0; i < 32; i += 8)
        tile[ty + i][tx] = v[((size_t)(b * SEQ + n0 + ty + i)) * DD1 + c0 + tx];
    __syncthreads();
    #pragma unroll
    for (int i = 0; i < 32; i += 8)
        vT[((size_t)(b * DD1 + c0 + ty + i)) * SEQ + n0 + tx] = tile[tx][ty + i];
}

// ---------------- causal per-channel convolution ----------------
// block = (n-tile of 512, one channel c), 128 threads.
// Each thread: 4 n's (tid + 128j) x 8 batches = 32 accumulators.
// out[b,n,c] = sum_{s<=n} a[c, n-s] * v[b,s,c]
__global__ __launch_bounds__(128)
void conv_kernel(const float* __restrict__ vT,     // (B, D1, N)
                 const float* __restrict__ aT,     // (D1, N), decayed
                 float* __restrict__ conv) {       // (B*N, D1)
    int c  = blockIdx.y;
    int n0 = blockIdx.x << 9;    // *512
    int tid = threadIdx.x;

    __shared__ __align__(16) float sv[BATCH][128];
    __shared__ float aw[640];

    float acc[4][8];
    #pragma unroll
    for (int j = 0; j < 4; ++j)
        #pragma unroll
        for (int b = 0; b < 8; ++b) acc[j][b] = 0.f;

    const float* ac = aT + (size_t)c * SEQ;
    int ntiles = (n0 + 512) >> 7;

    for (int st = 0; st < ntiles; ++st) {
        int s0 = st << 7;
        // coalesced fills
        #pragma unroll
        for (int b = 0; b < 8; ++b)
            sv[b][tid] = vT[((size_t)(b * DD1 + c)) * SEQ + s0 + tid];
        int t0 = n0 - s0 - 127;                  // aw[k] = a[t0+k], 0 if t<0
        #pragma unroll
        for (int j = 0; j < 5; ++j) {
            int k = tid + (j << 7);
            int t = t0 + k;
            aw[k] = (t >= 0 && t < SEQ) ? ac[t] : 0.f;
        }
        __syncthreads();

        #pragma unroll 4
        for (int ds = 0; ds < 128; ds += 4) {
            float4 vv[8];
            #pragma unroll
            for (int b = 0; b < 8; ++b) vv[b] = *(const float4*)&sv[b][ds];
            #pragma unroll
            for (int j = 0; j < 4; ++j) {
                int kb = tid + (j << 7) + 127 - ds;   // a index for s = s0+ds
                float a0 = aw[kb], a1 = aw[kb - 1], a2 = aw[kb - 2], a3 = aw[kb - 3];
                #pragma unroll
                for (int b = 0; b < 8; ++b)
                    acc[j][b] += a0 * vv[b].x + a1 * vv[b].y + a2 * vv[b].z + a3 * vv[b].w;
            }
        }
        __syncthreads();
    }

    #pragma unroll
    for (int j = 0; j < 4; ++j) {
        int n = n0 + tid + (j << 7);
        #pragma unroll
        for (int b = 0; b < 8; ++b)
            conv[((size_t)(b * SEQ + n)) * DD1 + c] = acc[j][b];
    }
}

// ================================================================
extern "C" void kernel_launch(void* const* d_in, const int* in_sizes, int n_in,
                              void* d_out, int out_size) {
    const float* x     = (const float*)d_in[0];
    const float* Wu    = (const float*)d_in[1];
    const float* bu    = (const float*)d_in[2];
    const float* Wv    = (const float*)d_in[3];
    const float* bv    = (const float*)d_in[4];
    const float* Wo    = (const float*)d_in[5];
    const float* bo    = (const float*)d_in[6];
    const float* rWin  = (const float*)d_in[7];
    const float* rbin  = (const float*)d_in[8];
    const float* rW    = (const float*)d_in[9];
    const float* rb    = (const float*)d_in[10];
    const float* rWout = (const float*)d_in[11];
    const float* rbout = (const float*)d_in[12];
    float* out = (float*)d_out;

    float *u, *v, *vT, *cv, *h, *s, *cf, *aT;
    cudaGetSymbolAddress((void**)&u,  g_u);
    cudaGetSymbolAddress((void**)&v,  g_vbuf);
    cudaGetSymbolAddress((void**)&vT, g_vT);
    cudaGetSymbolAddress((void**)&cv, g_conv);
    cudaGetSymbolAddress((void**)&h,  g_h);
    cudaGetSymbolAddress((void**)&s,  g_s);
    cudaGetSymbolAddress((void**)&cf, g_coeffs);
    cudaGetSymbolAddress((void**)&aT, g_acoefT);

    // ---- RPE MLP (tiny) ----
    rpe_init_kernel<<<(SEQ * RDIM + 255) / 256, 256>>>(rWin, rbin, h);
    for (int i = 0; i < 3; ++i) {
        srms_relu_kernel<<<SEQ, 256>>>(h, s);
        sgemm_kernel<0, 0><<<dim3(RDIM / 128, SEQ / 128), 256>>>(
            s, nullptr, rW + (size_t)i * RDIM * RDIM, rb + i * RDIM, h,
            SEQ, RDIM, RDIM);
    }
    srms_relu_kernel<<<SEQ, 256>>>(h, s);
    sgemm_kernel<0, 0><<<dim3(DD1 / 128, SEQ / 128), 256>>>(
        s, nullptr, rWout, rbout, cf, SEQ, DD1, RDIM);
    coeff_scale_transpose<<<(SEQ * DD1 + 255) / 256, 256>>>(cf, aT);

    // ---- u, v projections with silu ----
    sgemm_kernel<1, 0><<<dim3(DD1 / 128, MROWS / 128), 256>>>(
        x, nullptr, Wu, bu, u, MROWS, DD1, EMB);
    sgemm_kernel<1, 0><<<dim3(DD1 / 128, MROWS / 128), 256>>>(
        x, nullptr, Wv, bv, v, MROWS, DD1, EMB);

    // ---- causal conv ----
    transpose_v_kernel<<<dim3(SEQ / 32, DD1 / 32, BATCH), dim3(32, 8)>>>(v, vT);
    conv_kernel<<<dim3(SEQ / 512, DD1), 128>>>(vT, aT, cv);

    // ---- gated output GEMM: out = (u .* conv) @ Wo + bo ----
    sgemm_kernel<0, 1><<<dim3(EMB / 128, MROWS / 128), 256>>>(
        u, cv, Wo, bo, out, MROWS, EMB, DD1);
}

// round 10
// speedup vs baseline: 1.2283x; 1.2238x over previous
#include <cuda_runtime.h>
#include <math.h>

typedef unsigned long long ull;

#define BATCH 8
#define SEQ   2048
#define EMB   512
#define DD1   1536
#define RDIM  512
#define MROWS (BATCH*SEQ)      // 16384
#define GAMMA_F 0.99f

// ---- device-global scratch (no allocations allowed) ----
__device__ float g_u[MROWS*DD1];      // silu(x@Wu+bu)           (M, D1)
__device__ float g_vbuf[MROWS*DD1];   // v (M,D1), later convT (B,D1,N)
__device__ float g_vT[MROWS*DD1];     // v transposed            (B, D1, N)
__device__ float g_conv[MROWS*DD1];   // conv result             (M, D1)
__device__ float g_h[SEQ*RDIM];       // rpe hidden
__device__ float g_s[SEQ*RDIM];       // relu(srms(h))
__device__ float g_coeffs[SEQ*DD1];   // rpe output              (N, D1)
__device__ float g_acoefT[DD1*SEQ];   // decayed coeffs, transposed (D1, N)

// ---------------- packed f32x2 helpers ----------------
__device__ __forceinline__ void ffma2(ull &d, ull a, ull b) {
    asm("fma.rn.f32x2 %0, %1, %2, %0;" : "+l"(d) : "l"(a), "l"(b));
}
__device__ __forceinline__ ull pack2(float lo, float hi) {
    ull r; asm("mov.b64 %0, {%1, %2};" : "=l"(r) : "f"(lo), "f"(hi)); return r;
}
__device__ __forceinline__ void unpack2(ull v, float &lo, float &hi) {
    asm("mov.b64 {%0, %1}, %2;" : "=f"(lo), "=f"(hi) : "l"(v));
}

// ---------------- RPE init: h[n,r] = n*Win[r] + bin[r] ----------------
__global__ void rpe_init_kernel(const float* __restrict__ Win,
                                const float* __restrict__ bin,
                                float* __restrict__ h) {
    int g = blockIdx.x * blockDim.x + threadIdx.x;
    if (g >= SEQ * RDIM) return;
    int n = g >> 9;
    int r = g & 511;
    h[g] = (float)n * Win[r] + bin[r];
}

// --------- srms + relu over rows of width 512 ---------
__global__ void srms_relu_kernel(const float* __restrict__ in,
                                 float* __restrict__ out) {
    int row = blockIdx.x;
    const float* p = in + (size_t)row * RDIM;
    int tid = threadIdx.x;                 // 256 threads
    float v0 = p[tid], v1 = p[tid + 256];
    float ss = v0 * v0 + v1 * v1;
    #pragma unroll
    for (int o = 16; o > 0; o >>= 1) ss += __shfl_xor_sync(0xffffffffu, ss, o);
    __shared__ float ws[8];
    if ((tid & 31) == 0) ws[tid >> 5] = ss;
    __syncthreads();
    float tot = 0.f;
    #pragma unroll
    for (int i = 0; i < 8; ++i) tot += ws[i];
    float scale = 1.f / (sqrtf(tot * (1.f / (float)RDIM)) + 1e-6f);
    out[(size_t)row * RDIM + tid]       = fmaxf(v0 * scale, 0.f);
    out[(size_t)row * RDIM + tid + 256] = fmaxf(v1 * scale, 0.f);
}

// ---------------- GEMM v2: C = act((A [* A2]) @ B + bias) ----------------
// 128 threads, 128x128 tile, BK=8, double-buffered smem, f32x2 FMA.
// Thread microtile: 16 rows (8 float2 pairs) x 8 cols (split 4+4).
template<int ACT, int FUSE>
__global__ __launch_bounds__(128)
void gemm2_kernel(const float* __restrict__ A, const float* __restrict__ A2,
                  const float* __restrict__ B, const float* __restrict__ bias,
                  float* __restrict__ C, int M, int N, int K)
{
    __shared__ __align__(16) float As[2][8][128];   // [buf][k][m]
    __shared__ __align__(16) float Bs[2][8][128];   // [buf][k][n]

    const int tid  = threadIdx.x;
    const int row0 = blockIdx.y * 128;
    const int col0 = blockIdx.x * 128;
    const int rbase = (tid >> 4) * 16;      // 16 rows per thread
    const int c1 = (tid & 15) * 4;          // cols c1..c1+3 and c2..c2+3
    const int c2 = c1 + 64;

    // global load mapping
    const float* Ap  = A + (size_t)(row0 + tid) * K;          // row=tid, 8 ks
    const float* A2p = A2 + (size_t)(row0 + tid) * K;         // used iff FUSE
    const int brow = tid >> 4;                                // k-row 0..7
    const int bc   = (tid & 15) * 4;
    const float* Bp = B + (size_t)brow * N + col0 + bc;

    ull acc[8][8];
    #pragma unroll
    for (int i = 0; i < 8; ++i)
        #pragma unroll
        for (int j = 0; j < 8; ++j) acc[i][j] = 0ull;

    const int nk = K >> 3;

    float4 ra0, ra1, rb0, rb1;
    // ---- prologue: load tile 0, stage into buf 0 ----
    ra0 = *(const float4*)Ap;
    ra1 = *(const float4*)(Ap + 4);
    if (FUSE) {
        float4 m0 = *(const float4*)A2p, m1 = *(const float4*)(A2p + 4);
        ra0.x *= m0.x; ra0.y *= m0.y; ra0.z *= m0.z; ra0.w *= m0.w;
        ra1.x *= m1.x; ra1.y *= m1.y; ra1.z *= m1.z; ra1.w *= m1.w;
    }
    rb0 = *(const float4*)Bp;
    rb1 = *(const float4*)(Bp + 64);
    As[0][0][tid] = ra0.x; As[0][1][tid] = ra0.y;
    As[0][2][tid] = ra0.z; As[0][3][tid] = ra0.w;
    As[0][4][tid] = ra1.x; As[0][5][tid] = ra1.y;
    As[0][6][tid] = ra1.z; As[0][7][tid] = ra1.w;
    *(float4*)&Bs[0][brow][bc]      = rb0;
    *(float4*)&Bs[0][brow][bc + 64] = rb1;
    __syncthreads();

    int cur = 0;
    for (int kt = 0; kt < nk; ++kt) {
        const bool has = (kt + 1 < nk);
        if (has) {
            Ap += 8; Bp += (size_t)8 * N;
            ra0 = *(const float4*)Ap;
            ra1 = *(const float4*)(Ap + 4);
            if (FUSE) {
                A2p += 8;
                float4 m0 = *(const float4*)A2p, m1 = *(const float4*)(A2p + 4);
                ra0.x *= m0.x; ra0.y *= m0.y; ra0.z *= m0.z; ra0.w *= m0.w;
                ra1.x *= m1.x; ra1.y *= m1.y; ra1.z *= m1.z; ra1.w *= m1.w;
            }
            rb0 = *(const float4*)Bp;
            rb1 = *(const float4*)(Bp + 64);
        }

        #pragma unroll
        for (int k = 0; k < 8; ++k) {
            union { float4 f; ull u[2]; } q0, q1, q2, q3;
            q0.f = *(const float4*)&As[cur][k][rbase];        // broadcast LDS
            q1.f = *(const float4*)&As[cur][k][rbase + 4];
            q2.f = *(const float4*)&As[cur][k][rbase + 8];
            q3.f = *(const float4*)&As[cur][k][rbase + 12];
            ull ar[8] = { q0.u[0], q0.u[1], q1.u[0], q1.u[1],
                          q2.u[0], q2.u[1], q3.u[0], q3.u[1] };
            float4 b0 = *(const float4*)&Bs[cur][k][c1];      // conflict-free
            float4 b1 = *(const float4*)&Bs[cur][k][c2];
            ull bs[8] = { pack2(b0.x, b0.x), pack2(b0.y, b0.y),
                          pack2(b0.z, b0.z), pack2(b0.w, b0.w),
                          pack2(b1.x, b1.x), pack2(b1.y, b1.y),
                          pack2(b1.z, b1.z), pack2(b1.w, b1.w) };
            #pragma unroll
            for (int i = 0; i < 8; ++i)
                #pragma unroll
                for (int j = 0; j < 8; ++j)
                    ffma2(acc[i][j], ar[i], bs[j]);
        }

        if (has) {
            const int nxt = cur ^ 1;
            As[nxt][0][tid] = ra0.x; As[nxt][1][tid] = ra0.y;
            As[nxt][2][tid] = ra0.z; As[nxt][3][tid] = ra0.w;
            As[nxt][4][tid] = ra1.x; As[nxt][5][tid] = ra1.y;
            As[nxt][6][tid] = ra1.z; As[nxt][7][tid] = ra1.w;
            *(float4*)&Bs[nxt][brow][bc]      = rb0;
            *(float4*)&Bs[nxt][brow][bc + 64] = rb1;
        }
        __syncthreads();
        cur ^= 1;
    }

    // ---- epilogue ----
    float4 bb1 = *(const float4*)&bias[col0 + c1];
    float4 bb2 = *(const float4*)&bias[col0 + c2];
    float bb[8] = { bb1.x, bb1.y, bb1.z, bb1.w, bb2.x, bb2.y, bb2.z, bb2.w };
    #pragma unroll
    for (int i = 0; i < 8; ++i) {
        const int r = row0 + rbase + 2 * i;
        float e[8], o[8];
        #pragma unroll
        for (int j = 0; j < 8; ++j) {
            float lo, hi; unpack2(acc[i][j], lo, hi);
            lo += bb[j]; hi += bb[j];
            if (ACT) {
                lo = lo / (1.f + __expf(-lo));
                hi = hi / (1.f + __expf(-hi));
            }
            e[j] = lo; o[j] = hi;
        }
        *(float4*)&C[(size_t)r * N + col0 + c1]       = make_float4(e[0], e[1], e[2], e[3]);
        *(float4*)&C[(size_t)(r + 1) * N + col0 + c1] = make_float4(o[0], o[1], o[2], o[3]);
        *(float4*)&C[(size_t)r * N + col0 + c2]       = make_float4(e[4], e[5], e[6], e[7]);
        *(float4*)&C[(size_t)(r + 1) * N + col0 + c2] = make_float4(o[4], o[5], o[6], o[7]);
    }
}

// ---- scale by gamma^t and transpose coeffs (N,D1) -> (D1,N) ----
__global__ void coeff_scale_transpose(const float* __restrict__ coeffs,
                                      float* __restrict__ aT) {
    int g = blockIdx.x * blockDim.x + threadIdx.x;
    if (g >= SEQ * DD1) return;
    int t = g / DD1;
    int c = g - t * DD1;
    float dec = (t == 0) ? 1.f : powf(GAMMA_F, (float)t);
    aT[(size_t)c * SEQ + t] = coeffs[g] * dec;
}

// ---- transpose v: (B,N,D1) -> (B,D1,N) ----
__global__ void transpose_v_kernel(const float* __restrict__ v,
                                   float* __restrict__ vT) {
    __shared__ float tile[32][33];
    int b  = blockIdx.z;
    int n0 = blockIdx.x << 5;
    int c0 = blockIdx.y << 5;
    int tx = threadIdx.x, ty = threadIdx.y;   // (32,8)
    #pragma unroll
    for (int i = 0; i < 32; i += 8)
        tile[ty + i][tx] = v[((size_t)(b * SEQ + n0 + ty + i)) * DD1 + c0 + tx];
    __syncthreads();
    #pragma unroll
    for (int i = 0; i < 32; i += 8)
        vT[((size_t)(b * DD1 + c0 + ty + i)) * SEQ + n0 + tx] = tile[tx][ty + i];
}

// ---- transpose back: (B,D1,N) -> (B,N,D1) ----
__global__ void transpose_back_kernel(const float* __restrict__ ct,
                                      float* __restrict__ out) {
    __shared__ float tile[32][33];
    int b  = blockIdx.z;
    int c0 = blockIdx.x << 5;
    int n0 = blockIdx.y << 5;
    int tx = threadIdx.x, ty = threadIdx.y;   // (32,8)
    #pragma unroll
    for (int i = 0; i < 32; i += 8)
        tile[ty + i][tx] = ct[((size_t)(b * DD1 + c0 + ty + i)) * SEQ + n0 + tx];
    __syncthreads();
    #pragma unroll
    for (int i = 0; i < 32; i += 8)
        out[((size_t)(b * SEQ + n0 + ty + i)) * DD1 + c0 + tx] = tile[tx][ty + i];
}

// ---------------- causal per-channel convolution (f32x2) ----------------
// block = (512-n tile, one channel c), 128 threads.
// Thread handles n-pairs: n = n0 + j*256 + 2*tid + {0,1}, j in {0,1}, all 8 batches.
// Writes convT in (B, D1, N) layout with coalesced float2 stores.
__global__ __launch_bounds__(128)
void conv2_kernel(const float* __restrict__ vT,     // (B, D1, N)
                  const float* __restrict__ aT,     // (D1, N), decayed
                  float* __restrict__ convT) {      // (B, D1, N)
    const int c   = blockIdx.y;
    const int n0  = blockIdx.x << 9;
    const int tid = threadIdx.x;

    __shared__ __align__(16) ull sv2[BATCH][128];   // splatted v: {v,v}
    __shared__ __align__(16) ull aw2[640];          // paired a: {a[t], a[t+1]}

    ull acc[2][8];
    #pragma unroll
    for (int j = 0; j < 2; ++j)
        #pragma unroll
        for (int b = 0; b < 8; ++b) acc[j][b] = 0ull;

    const float* ac = aT + (size_t)c * SEQ;
    const int ntiles = (n0 + 512) >> 7;

    for (int st = 0; st < ntiles; ++st) {
        const int s0 = st << 7;
        #pragma unroll
        for (int b = 0; b < 8; ++b) {
            float x = vT[((size_t)(b * DD1 + c)) * SEQ + s0 + tid];
            sv2[b][tid] = pack2(x, x);
        }
        const int t0 = n0 - s0 - 127;
        #pragma unroll
        for (int jj = 0; jj < 5; ++jj) {
            int k = tid + (jj << 7);
            if (k < 640) {
                int t = t0 + k;
                float x0 = (t >= 0 && t < SEQ) ? ac[t] : 0.f;
                float x1 = (t + 1 >= 0 && t + 1 < SEQ) ? ac[t + 1] : 0.f;
                aw2[k] = pack2(x0, x1);
            }
        }
        __syncthreads();

        #pragma unroll 4
        for (int ds = 0; ds < 128; ds += 4) {
            ull ap[2][4];
            #pragma unroll
            for (int j = 0; j < 2; ++j) {
                int kb = (j << 8) + 2 * tid + 127 - ds;
                ap[j][0] = aw2[kb];     ap[j][1] = aw2[kb - 1];
                ap[j][2] = aw2[kb - 2]; ap[j][3] = aw2[kb - 3];
            }
            #pragma unroll
            for (int b = 0; b < 8; ++b) {
                ull v0 = sv2[b][ds],     v1 = sv2[b][ds + 1];
                ull v2 = sv2[b][ds + 2], v3 = sv2[b][ds + 3];
                #pragma unroll
                for (int j = 0; j < 2; ++j) {
                    ffma2(acc[j][b], ap[j][0], v0);
                    ffma2(acc[j][b], ap[j][1], v1);
                    ffma2(acc[j][b], ap[j][2], v2);
                    ffma2(acc[j][b], ap[j][3], v3);
                }
            }
        }
        __syncthreads();
    }

    #pragma unroll
    for (int j = 0; j < 2; ++j) {
        int n = n0 + (j << 8) + 2 * tid;
        #pragma unroll
        for (int b = 0; b < 8; ++b) {
            float lo, hi; unpack2(acc[j][b], lo, hi);
            *(float2*)&convT[((size_t)(b * DD1 + c)) * SEQ + n] = make_float2(lo, hi);
        }
    }
}

// ================================================================
extern "C" void kernel_launch(void* const* d_in, const int* in_sizes, int n_in,
                              void* d_out, int out_size) {
    const float* x     = (const float*)d_in[0];
    const float* Wu    = (const float*)d_in[1];
    const float* bu    = (const float*)d_in[2];
    const float* Wv    = (const float*)d_in[3];
    const float* bv    = (const float*)d_in[4];
    const float* Wo    = (const float*)d_in[5];
    const float* bo    = (const float*)d_in[6];
    const float* rWin  = (const float*)d_in[7];
    const float* rbin  = (const float*)d_in[8];
    const float* rW    = (const float*)d_in[9];
    const float* rb    = (const float*)d_in[10];
    const float* rWout = (const float*)d_in[11];
    const float* rbout = (const float*)d_in[12];
    float* out = (float*)d_out;

    float *u, *v, *vT, *cv, *h, *s, *cf, *aT;
    cudaGetSymbolAddress((void**)&u,  g_u);
    cudaGetSymbolAddress((void**)&v,  g_vbuf);
    cudaGetSymbolAddress((void**)&vT, g_vT);
    cudaGetSymbolAddress((void**)&cv, g_conv);
    cudaGetSymbolAddress((void**)&h,  g_h);
    cudaGetSymbolAddress((void**)&s,  g_s);
    cudaGetSymbolAddress((void**)&cf, g_coeffs);
    cudaGetSymbolAddress((void**)&aT, g_acoefT);

    // ---- RPE MLP (small) ----
    rpe_init_kernel<<<(SEQ * RDIM + 255) / 256, 256>>>(rWin, rbin, h);
    for (int i = 0; i < 3; ++i) {
        srms_relu_kernel<<<SEQ, 256>>>(h, s);
        gemm2_kernel<0, 0><<<dim3(RDIM / 128, SEQ / 128), 128>>>(
            s, nullptr, rW + (size_t)i * RDIM * RDIM, rb + i * RDIM, h,
            SEQ, RDIM, RDIM);
    }
    srms_relu_kernel<<<SEQ, 256>>>(h, s);
    gemm2_kernel<0, 0><<<dim3(DD1 / 128, SEQ / 128), 128>>>(
        s, nullptr, rWout, rbout, cf, SEQ, DD1, RDIM);
    coeff_scale_transpose<<<(SEQ * DD1 + 255) / 256, 256>>>(cf, aT);

    // ---- u, v projections with silu ----
    gemm2_kernel<1, 0><<<dim3(DD1 / 128, MROWS / 128), 128>>>(
        x, nullptr, Wu, bu, u, MROWS, DD1, EMB);
    gemm2_kernel<1, 0><<<dim3(DD1 / 128, MROWS / 128), 128>>>(
        x, nullptr, Wv, bv, v, MROWS, DD1, EMB);

    // ---- causal conv (writes convT into g_vbuf, then transpose back) ----
    transpose_v_kernel<<<dim3(SEQ / 32, DD1 / 32, BATCH), dim3(32, 8)>>>(v, vT);
    conv2_kernel<<<dim3(SEQ / 512, DD1), 128>>>(vT, aT, v /* reuse as convT */);
    transpose_back_kernel<<<dim3(DD1 / 32, SEQ / 32, BATCH), dim3(32, 8)>>>(v, cv);

    // ---- gated output GEMM: out = (u .* conv) @ Wo + bo ----
    gemm2_kernel<0, 1><<<dim3(EMB / 128, MROWS / 128), 128>>>(
        u, cv, Wo, bo, out, MROWS, EMB, DD1);
}

// round 13
// speedup vs baseline: 1.4842x; 1.2083x over previous
#include <cuda_runtime.h>
#include <cuda_bf16.h>
#include <math.h>

typedef unsigned long long ull;
typedef unsigned int u32;
typedef unsigned short u16;

#define BATCH 8
#define SEQ   2048
#define EMB   512
#define DD1   1536
#define RDIM  512
#define MROWS (BATCH*SEQ)      // 16384
#define GAMMA_F 0.99f

// ---- device-global scratch ----
__device__ float g_u[MROWS*DD1];
__device__ float g_vbuf[MROWS*DD1];   // v, then convT (B,D1,N)
__device__ float g_vT[MROWS*DD1];     // (B, D1, N)
__device__ float g_conv[MROWS*DD1];   // conv (M, D1)
__device__ float g_h[SEQ*RDIM];
__device__ float g_s[SEQ*RDIM];
__device__ float g_coeffs[SEQ*DD1];
__device__ float g_acoefT[DD1*SEQ];
// bf16 splits
__device__ u16 g_xhi[MROWS*EMB];
__device__ u16 g_xlo[MROWS*EMB];
__device__ u16 g_ghi[MROWS*DD1];
__device__ u16 g_glo[MROWS*DD1];
__device__ u16 g_wthi[DD1*EMB];       // transposed weight splits (N,K) K-major
__device__ u16 g_wtlo[DD1*EMB];

// ---------------- f32x2 helpers ----------------
__device__ __forceinline__ void ffma2(ull &d, ull a, ull b) {
    asm("fma.rn.f32x2 %0, %1, %2, %0;" : "+l"(d) : "l"(a), "l"(b));
}
__device__ __forceinline__ ull pack2(float lo, float hi) {
    ull r; asm("mov.b64 %0, {%1, %2};" : "=l"(r) : "f"(lo), "f"(hi)); return r;
}
__device__ __forceinline__ void unpack2(ull v, float &lo, float &hi) {
    asm("mov.b64 {%0, %1}, %2;" : "=f"(lo), "=f"(hi) : "l"(v));
}
__device__ __forceinline__ u32 smem_u32(const void* p) {
    u32 a; asm("{ .reg .u64 t; cvta.to.shared.u64 t, %1; cvt.u32.u64 %0, t; }"
               : "=r"(a) : "l"(p));
    return a;
}

// ---------------- mma.sync / ldmatrix / cp.async ----------------
__device__ __forceinline__ void mma_bf16(float* c, const u32* a, const u32* b) {
    asm volatile("mma.sync.aligned.m16n8k16.row.col.f32.bf16.bf16.f32 "
        "{%0,%1,%2,%3}, {%4,%5,%6,%7}, {%8,%9}, {%0,%1,%2,%3};"
        : "+f"(c[0]), "+f"(c[1]), "+f"(c[2]), "+f"(c[3])
        : "r"(a[0]), "r"(a[1]), "r"(a[2]), "r"(a[3]), "r"(b[0]), "r"(b[1]));
}
__device__ __forceinline__ void ldsm4(u32* r, u32 addr) {
    asm volatile("ldmatrix.sync.aligned.m8n8.x4.shared.b16 {%0,%1,%2,%3}, [%4];"
        : "=r"(r[0]), "=r"(r[1]), "=r"(r[2]), "=r"(r[3]) : "r"(addr));
}
__device__ __forceinline__ void cp16(u32 saddr, const void* g) {
    asm volatile("cp.async.cg.shared.global [%0], [%1], 16;" :: "r"(saddr), "l"(g));
}
__device__ __forceinline__ void cp_commit() { asm volatile("cp.async.commit_group;" ::: "memory"); }
__device__ __forceinline__ void cp_wait0()  { asm volatile("cp.async.wait_group 0;" ::: "memory"); }

// ---------------- RPE init ----------------
__global__ void rpe_init_kernel(const float* __restrict__ Win,
                                const float* __restrict__ bin,
                                float* __restrict__ h) {
    int g = blockIdx.x * blockDim.x + threadIdx.x;
    if (g >= SEQ * RDIM) return;
    int n = g >> 9, r = g & 511;
    h[g] = (float)n * Win[r] + bin[r];
}

// --------- srms + relu rows of 512 ---------
__global__ void srms_relu_kernel(const float* __restrict__ in,
                                 float* __restrict__ out) {
    int row = blockIdx.x;
    const float* p = in + (size_t)row * RDIM;
    int tid = threadIdx.x;
    float v0 = p[tid], v1 = p[tid + 256];
    float ss = v0 * v0 + v1 * v1;
    #pragma unroll
    for (int o = 16; o > 0; o >>= 1) ss += __shfl_xor_sync(0xffffffffu, ss, o);
    __shared__ float ws[8];
    if ((tid & 31) == 0) ws[tid >> 5] = ss;
    __syncthreads();
    float tot = 0.f;
    #pragma unroll
    for (int i = 0; i < 8; ++i) tot += ws[i];
    float scale = 1.f / (sqrtf(tot * (1.f / (float)RDIM)) + 1e-6f);
    out[(size_t)row * RDIM + tid]       = fmaxf(v0 * scale, 0.f);
    out[(size_t)row * RDIM + tid + 256] = fmaxf(v1 * scale, 0.f);
}

// ---------------- f32x2 SGEMM (RPE only) ----------------
template<int ACT>
__global__ __launch_bounds__(128)
void gemm2_kernel(const float* __restrict__ A, const float* __restrict__ B,
                  const float* __restrict__ bias, float* __restrict__ C,
                  int M, int N, int K)
{
    __shared__ __align__(16) float As[2][8][128];
    __shared__ __align__(16) float Bs[2][8][128];
    const int tid  = threadIdx.x;
    const int row0 = blockIdx.y * 128, col0 = blockIdx.x * 128;
    const int rbase = (tid >> 4) * 16;
    const int c1 = (tid & 15) * 4, c2 = c1 + 64;
    const float* Ap = A + (size_t)(row0 + tid) * K;
    const int brow = tid >> 4, bc = (tid & 15) * 4;
    const float* Bp = B + (size_t)brow * N + col0 + bc;
    ull acc[8][8];
    #pragma unroll
    for (int i = 0; i < 8; ++i)
        #pragma unroll
        for (int j = 0; j < 8; ++j) acc[i][j] = 0ull;
    const int nk = K >> 3;
    float4 ra0, ra1, rb0, rb1;
    ra0 = *(const float4*)Ap; ra1 = *(const float4*)(Ap + 4);
    rb0 = *(const float4*)Bp; rb1 = *(const float4*)(Bp + 64);
    As[0][0][tid]=ra0.x; As[0][1][tid]=ra0.y; As[0][2][tid]=ra0.z; As[0][3][tid]=ra0.w;
    As[0][4][tid]=ra1.x; As[0][5][tid]=ra1.y; As[0][6][tid]=ra1.z; As[0][7][tid]=ra1.w;
    *(float4*)&Bs[0][brow][bc] = rb0; *(float4*)&Bs[0][brow][bc+64] = rb1;
    __syncthreads();
    int cur = 0;
    for (int kt = 0; kt < nk; ++kt) {
        const bool has = (kt + 1 < nk);
        if (has) {
            Ap += 8; Bp += (size_t)8 * N;
            ra0 = *(const float4*)Ap; ra1 = *(const float4*)(Ap + 4);
            rb0 = *(const float4*)Bp; rb1 = *(const float4*)(Bp + 64);
        }
        #pragma unroll
        for (int k = 0; k < 8; ++k) {
            union { float4 f; ull u[2]; } q0, q1, q2, q3;
            q0.f = *(const float4*)&As[cur][k][rbase];
            q1.f = *(const float4*)&As[cur][k][rbase + 4];
            q2.f = *(const float4*)&As[cur][k][rbase + 8];
            q3.f = *(const float4*)&As[cur][k][rbase + 12];
            ull ar[8] = { q0.u[0],q0.u[1],q1.u[0],q1.u[1],q2.u[0],q2.u[1],q3.u[0],q3.u[1] };
            float4 b0 = *(const float4*)&Bs[cur][k][c1];
            float4 b1 = *(const float4*)&Bs[cur][k][c2];
            ull bs[8] = { pack2(b0.x,b0.x),pack2(b0.y,b0.y),pack2(b0.z,b0.z),pack2(b0.w,b0.w),
                          pack2(b1.x,b1.x),pack2(b1.y,b1.y),pack2(b1.z,b1.z),pack2(b1.w,b1.w) };
            #pragma unroll
            for (int i = 0; i < 8; ++i)
                #pragma unroll
                for (int j = 0; j < 8; ++j) ffma2(acc[i][j], ar[i], bs[j]);
        }
        if (has) {
            const int nxt = cur ^ 1;
            As[nxt][0][tid]=ra0.x; As[nxt][1][tid]=ra0.y; As[nxt][2][tid]=ra0.z; As[nxt][3][tid]=ra0.w;
            As[nxt][4][tid]=ra1.x; As[nxt][5][tid]=ra1.y; As[nxt][6][tid]=ra1.z; As[nxt][7][tid]=ra1.w;
            *(float4*)&Bs[nxt][brow][bc] = rb0; *(float4*)&Bs[nxt][brow][bc+64] = rb1;
        }
        __syncthreads();
        cur ^= 1;
    }
    float4 bb1 = *(const float4*)&bias[col0 + c1];
    float4 bb2 = *(const float4*)&bias[col0 + c2];
    float bb[8] = { bb1.x,bb1.y,bb1.z,bb1.w, bb2.x,bb2.y,bb2.z,bb2.w };
    #pragma unroll
    for (int i = 0; i < 8; ++i) {
        const int r = row0 + rbase + 2 * i;
        float e[8], o[8];
        #pragma unroll
        for (int j = 0; j < 8; ++j) {
            float lo, hi; unpack2(acc[i][j], lo, hi);
            lo += bb[j]; hi += bb[j];
            if (ACT) { lo = lo/(1.f+__expf(-lo)); hi = hi/(1.f+__expf(-hi)); }
            e[j] = lo; o[j] = hi;
        }
        *(float4*)&C[(size_t)r*N + col0 + c1]     = make_float4(e[0],e[1],e[2],e[3]);
        *(float4*)&C[(size_t)(r+1)*N + col0 + c1] = make_float4(o[0],o[1],o[2],o[3]);
        *(float4*)&C[(size_t)r*N + col0 + c2]     = make_float4(e[4],e[5],e[6],e[7]);
        *(float4*)&C[(size_t)(r+1)*N + col0 + c2] = make_float4(o[4],o[5],o[6],o[7]);
    }
}

// ---- coeff decay + transpose ----
__global__ void coeff_scale_transpose(const float* __restrict__ coeffs,
                                      float* __restrict__ aT) {
    int g = blockIdx.x * blockDim.x + threadIdx.x;
    if (g >= SEQ * DD1) return;
    int t = g / DD1, c = g - t * DD1;
    float dec = (t == 0) ? 1.f : powf(GAMMA_F, (float)t);
    aT[(size_t)c * SEQ + t] = coeffs[g] * dec;
}

// ---- transposes ----
__global__ void transpose_v_kernel(const float* __restrict__ v, float* __restrict__ vT) {
    __shared__ float tile[32][33];
    int b = blockIdx.z, n0 = blockIdx.x << 5, c0 = blockIdx.y << 5;
    int tx = threadIdx.x, ty = threadIdx.y;
    #pragma unroll
    for (int i = 0; i < 32; i += 8)
        tile[ty + i][tx] = v[((size_t)(b * SEQ + n0 + ty + i)) * DD1 + c0 + tx];
    __syncthreads();
    #pragma unroll
    for (int i = 0; i < 32; i += 8)
        vT[((size_t)(b * DD1 + c0 + ty + i)) * SEQ + n0 + tx] = tile[tx][ty + i];
}
__global__ void transpose_back_kernel(const float* __restrict__ ct, float* __restrict__ out) {
    __shared__ float tile[32][33];
    int b = blockIdx.z, c0 = blockIdx.x << 5, n0 = blockIdx.y << 5;
    int tx = threadIdx.x, ty = threadIdx.y;
    #pragma unroll
    for (int i = 0; i < 32; i += 8)
        tile[ty + i][tx] = ct[((size_t)(b * DD1 + c0 + ty + i)) * SEQ + n0 + tx];
    __syncthreads();
    #pragma unroll
    for (int i = 0; i < 32; i += 8)
        out[((size_t)(b * SEQ + n0 + ty + i)) * DD1 + c0 + tx] = tile[tx][ty + i];
}

// ---------------- conv v3: batch-paired f32x2 ----------------
__global__ __launch_bounds__(128)
void conv3_kernel(const float* __restrict__ vT,     // (B, D1, N)
                  const float* __restrict__ aT,     // (D1, N) decayed
                  float* __restrict__ convT) {      // (B, D1, N)
    const int c = blockIdx.y, n0 = blockIdx.x << 9, tid = threadIdx.x;
    __shared__ __align__(16) ull svp[4][128];   // {v[b], v[b+4]}
    __shared__ __align__(16) ull awS[640];      // splat {a,a}
    ull acc[4][4];
    #pragma unroll
    for (int j = 0; j < 4; ++j)
        #pragma unroll
        for (int bp = 0; bp < 4; ++bp) acc[j][bp] = 0ull;
    const float* ac = aT + (size_t)c * SEQ;
    const int ntiles = (n0 + 512) >> 7;
    for (int st = 0; st < ntiles; ++st) {
        const int s0 = st << 7;
        #pragma unroll
        for (int bp = 0; bp < 4; ++bp) {
            float a0 = vT[((size_t)(bp * DD1 + c)) * SEQ + s0 + tid];
            float a1 = vT[((size_t)((bp + 4) * DD1 + c)) * SEQ + s0 + tid];
            svp[bp][tid] = pack2(a0, a1);
        }
        const int t0 = n0 - s0 - 127;
        #pragma unroll
        for (int jj = 0; jj < 5; ++jj) {
            int k = tid + (jj << 7);
            int t = t0 + k;
            float a = (t >= 0 && t < SEQ) ? ac[t] : 0.f;
            awS[k] = pack2(a, a);
        }
        __syncthreads();
        #pragma unroll 4
        for (int sl = 0; sl < 128; ++sl) {
            ull v0 = svp[0][sl], v1 = svp[1][sl], v2 = svp[2][sl], v3 = svp[3][sl];
            int kb = 127 + tid - sl;
            #pragma unroll
            for (int j = 0; j < 4; ++j) {
                ull aa = awS[kb + (j << 7)];
                ffma2(acc[j][0], aa, v0);
                ffma2(acc[j][1], aa, v1);
                ffma2(acc[j][2], aa, v2);
                ffma2(acc[j][3], aa, v3);
            }
        }
        __syncthreads();
    }
    #pragma unroll
    for (int j = 0; j < 4; ++j) {
        int n = n0 + (j << 7) + tid;
        #pragma unroll
        for (int bp = 0; bp < 4; ++bp) {
            float lo, hi; unpack2(acc[j][bp], lo, hi);
            convT[((size_t)(bp * DD1 + c)) * SEQ + n]       = lo;
            convT[((size_t)((bp + 4) * DD1 + c)) * SEQ + n] = hi;
        }
    }
}

// ---------------- bf16 split kernels ----------------
__device__ __forceinline__ u16 bf_hi(float x) {
    __nv_bfloat16 b = __float2bfloat16(x);
    return *(u16*)&b;
}
__device__ __forceinline__ float bf_val(u16 b) {
    __nv_bfloat16 h = *(__nv_bfloat16*)&b;
    return __bfloat162float(h);
}
__global__ void split_kernel(const float* __restrict__ x, u16* __restrict__ hi,
                             u16* __restrict__ lo, int n) {
    int g = (blockIdx.x * blockDim.x + threadIdx.x) << 2;
    if (g >= n) return;
    float4 v = *(const float4*)(x + g);
    u16 h[4], l[4];
    float vv[4] = { v.x, v.y, v.z, v.w };
    #pragma unroll
    for (int i = 0; i < 4; ++i) {
        h[i] = bf_hi(vv[i]);
        l[i] = bf_hi(vv[i] - bf_val(h[i]));
    }
    *(uint2*)&hi[g] = *(uint2*)h;
    *(uint2*)&lo[g] = *(uint2*)l;
}
__global__ void gate_split_kernel(const float* __restrict__ u, const float* __restrict__ cv,
                                  u16* __restrict__ hi, u16* __restrict__ lo, int n) {
    int g = (blockIdx.x * blockDim.x + threadIdx.x) << 2;
    if (g >= n) return;
    float4 a = *(const float4*)(u + g);
    float4 b = *(const float4*)(cv + g);
    float vv[4] = { a.x * b.x, a.y * b.y, a.z * b.z, a.w * b.w };
    u16 h[4], l[4];
    #pragma unroll
    for (int i = 0; i < 4; ++i) {
        h[i] = bf_hi(vv[i]);
        l[i] = bf_hi(vv[i] - bf_val(h[i]));
    }
    *(uint2*)&hi[g] = *(uint2*)h;
    *(uint2*)&lo[g] = *(uint2*)l;
}
// transpose W (K,N) -> Wt (N,K) with hi/lo split
__global__ void wsplit_t_kernel(const float* __restrict__ W, u16* __restrict__ hi,
                                u16* __restrict__ lo, int K, int N) {
    __shared__ float tile[32][33];
    int n0 = blockIdx.x << 5, k0 = blockIdx.y << 5;
    int tx = threadIdx.x, ty = threadIdx.y;   // (32,8)
    #pragma unroll
    for (int i = 0; i < 32; i += 8)
        tile[ty + i][tx] = W[(size_t)(k0 + ty + i) * N + n0 + tx];
    __syncthreads();
    #pragma unroll
    for (int i = 0; i < 32; i += 8) {
        float v = tile[tx][ty + i];            // W[k0+tx][n0+ty+i]
        size_t o = (size_t)(n0 + ty + i) * K + k0 + tx;
        u16 h = bf_hi(v);
        hi[o] = h;
        lo[o] = bf_hi(v - bf_val(h));
    }
}

// ---------------- HMMA split-GEMM (mma.sync bf16, 3 products) ----------------
// C = act((Ah+Al)@(Bh+Bl)^T + bias). A: (M,K) u16, B: (N,K) u16 (K-major).
// 128x128x64 tiles, 256 threads, 8 warps (2 m x 4 n), cp.async double buffer.
#define PITCH   72                      // u16 per smem row (64 data + 8 pad)
#define TILE_B  (128*PITCH*2)           // 18432 B
#define STAGE_B (4*TILE_B)              // 73728 B
#define MM_SMEM (2*STAGE_B)             // 147456 B

// Each thread (r = t>>1, hh = t&1) copies 64 B (elements hh*32 .. hh*32+31)
// of row r in each of the 4 tiles: full 128 B row covered by hh in {0,1}.
__device__ __forceinline__ void fill_stage(u32 st,
        const u16* __restrict__ Ah, const u16* __restrict__ Al,
        const u16* __restrict__ Bh, const u16* __restrict__ Bl,
        int row0, int col0, int K, int kc, int t) {
    const int r = t >> 1, hh = t & 1;
    const u32 so = (u32)(r * PITCH + hh * 32) * 2;
    const size_t goA = (size_t)(row0 + r) * K + (kc << 6) + hh * 32;
    const size_t goB = (size_t)(col0 + r) * K + (kc << 6) + hh * 32;
    #pragma unroll
    for (int e = 0; e < 4; ++e) {
        cp16(st + so + e*16,              Ah + goA + e*8);
        cp16(st + TILE_B + so + e*16,     Al + goA + e*8);
        cp16(st + 2*TILE_B + so + e*16,   Bh + goB + e*8);
        cp16(st + 3*TILE_B + so + e*16,   Bl + goB + e*8);
    }
}

template<int ACT>
__global__ __launch_bounds__(256, 1)
void gemm_mma_kernel(const u16* __restrict__ Ah, const u16* __restrict__ Al,
                     const u16* __restrict__ Bh, const u16* __restrict__ Bl,
                     const float* __restrict__ bias, float* __restrict__ C,
                     int M, int N, int K)
{
    extern __shared__ char dsm[];
    const u32 sb = smem_u32(dsm);
    const int tid = threadIdx.x, lane = tid & 31, wid = tid >> 5;
    const int wm = wid & 1;            // 0/1 -> 64-row block
    const int wn = wid >> 1;           // 0..3 -> 32-col block
    const int row0 = blockIdx.y * 128, col0 = blockIdx.x * 128;
    const int nkc = K >> 6;

    const int q = lane >> 3, l7 = lane & 7;
    // A ldmatrix.x4: matrices (mlo,klo),(mhi,klo),(mlo,khi),(mhi,khi)
    const u32 aoff = (u32)((wm*64 + (q & 1)*8 + l7) * PITCH + (q >> 1)*8) * 2;
    // B ldmatrix.x4: matrices (nlo,klo),(nlo,khi),(nhi,klo),(nhi,khi)
    const u32 boff = (u32)((wn*32 + (q >> 1)*8 + l7) * PITCH + (q & 1)*8) * 2;

    float acc[4][4][4];
    #pragma unroll
    for (int i = 0; i < 4; ++i)
        #pragma unroll
        for (int j = 0; j < 4; ++j)
            #pragma unroll
            for (int r = 0; r < 4; ++r) acc[i][j][r] = 0.f;

    fill_stage(sb, Ah, Al, Bh, Bl, row0, col0, K, 0, tid);
    cp_commit();

    for (int kc = 0; kc < nkc; ++kc) {
        cp_wait0();
        __syncthreads();
        const u32 st = sb + (kc & 1) * STAGE_B;
        if (kc + 1 < nkc) {
            fill_stage(sb + ((kc + 1) & 1) * STAGE_B, Ah, Al, Bh, Bl,
                       row0, col0, K, kc + 1, tid);
            cp_commit();
        }
        #pragma unroll
        for (int ks = 0; ks < 4; ++ks) {
            u32 ah[4][4], al[4][4], bh[2][4], bl[2][4];
            #pragma unroll
            for (int i = 0; i < 4; ++i) {
                ldsm4(ah[i], st + aoff + i*2304 + ks*32);
                ldsm4(al[i], st + TILE_B + aoff + i*2304 + ks*32);
            }
            #pragma unroll
            for (int jj = 0; jj < 2; ++jj) {
                ldsm4(bh[jj], st + 2*TILE_B + boff + jj*2304 + ks*32);
                ldsm4(bl[jj], st + 3*TILE_B + boff + jj*2304 + ks*32);
            }
            #pragma unroll
            for (int i = 0; i < 4; ++i)
                #pragma unroll
                for (int jn = 0; jn < 4; ++jn)
                    mma_bf16(acc[i][jn], ah[i], &bh[jn >> 1][(jn & 1) * 2]);
            #pragma unroll
            for (int i = 0; i < 4; ++i)
                #pragma unroll
                for (int jn = 0; jn < 4; ++jn)
                    mma_bf16(acc[i][jn], ah[i], &bl[jn >> 1][(jn & 1) * 2]);
            #pragma unroll
            for (int i = 0; i < 4; ++i)
                #pragma unroll
                for (int jn = 0; jn < 4; ++jn)
                    mma_bf16(acc[i][jn], al[i], &bh[jn >> 1][(jn & 1) * 2]);
        }
    }

    const int mrow = lane >> 2, ncol = (lane & 3) * 2;
    #pragma unroll
    for (int i = 0; i < 4; ++i) {
        const int m = row0 + wm*64 + i*16 + mrow;
        #pragma unroll
        for (int jn = 0; jn < 4; ++jn) {
            const int n = col0 + wn*32 + jn*8 + ncol;
            const float b0 = bias[n], b1 = bias[n + 1];
            float c0 = acc[i][jn][0] + b0, c1 = acc[i][jn][1] + b1;
            float c2 = acc[i][jn][2] + b0, c3 = acc[i][jn][3] + b1;
            if (ACT) {
                c0 = c0/(1.f+__expf(-c0)); c1 = c1/(1.f+__expf(-c1));
                c2 = c2/(1.f+__expf(-c2)); c3 = c3/(1.f+__expf(-c3));
            }
            *(float2*)&C[(size_t)m * N + n]       = make_float2(c0, c1);
            *(float2*)&C[(size_t)(m + 8) * N + n] = make_float2(c2, c3);
        }
    }
}

// ================================================================
extern "C" void kernel_launch(void* const* d_in, const int* in_sizes, int n_in,
                              void* d_out, int out_size) {
    const float* x     = (const float*)d_in[0];
    const float* Wu    = (const float*)d_in[1];
    const float* bu    = (const float*)d_in[2];
    const float* Wv    = (const float*)d_in[3];
    const float* bv    = (const float*)d_in[4];
    const float* Wo    = (const float*)d_in[5];
    const float* bo    = (const float*)d_in[6];
    const float* rWin  = (const float*)d_in[7];
    const float* rbin  = (const float*)d_in[8];
    const float* rW    = (const float*)d_in[9];
    const float* rb    = (const float*)d_in[10];
    const float* rWout = (const float*)d_in[11];
    const float* rbout = (const float*)d_in[12];
    float* out = (float*)d_out;

    float *u, *v, *vT, *cv, *h, *s, *cf, *aT;
    u16 *xhi, *xlo, *ghi, *glo, *wthi, *wtlo;
    cudaGetSymbolAddress((void**)&u,  g_u);
    cudaGetSymbolAddress((void**)&v,  g_vbuf);
    cudaGetSymbolAddress((void**)&vT, g_vT);
    cudaGetSymbolAddress((void**)&cv, g_conv);
    cudaGetSymbolAddress((void**)&h,  g_h);
    cudaGetSymbolAddress((void**)&s,  g_s);
    cudaGetSymbolAddress((void**)&cf, g_coeffs);
    cudaGetSymbolAddress((void**)&aT, g_acoefT);
    cudaGetSymbolAddress((void**)&xhi, g_xhi);
    cudaGetSymbolAddress((void**)&xlo, g_xlo);
    cudaGetSymbolAddress((void**)&ghi, g_ghi);
    cudaGetSymbolAddress((void**)&glo, g_glo);
    cudaGetSymbolAddress((void**)&wthi, g_wthi);
    cudaGetSymbolAddress((void**)&wtlo, g_wtlo);

    cudaFuncSetAttribute(gemm_mma_kernel<0>, cudaFuncAttributeMaxDynamicSharedMemorySize, MM_SMEM);
    cudaFuncSetAttribute(gemm_mma_kernel<1>, cudaFuncAttributeMaxDynamicSharedMemorySize, MM_SMEM);

    // ---- split x into bf16 hi/lo ----
    split_kernel<<<(MROWS * EMB / 4 + 255) / 256, 256>>>(x, xhi, xlo, MROWS * EMB);

    // ---- RPE MLP (f32x2, exact) ----
    rpe_init_kernel<<<(SEQ * RDIM + 255) / 256, 256>>>(rWin, rbin, h);
    for (int i = 0; i < 3; ++i) {
        srms_relu_kernel<<<SEQ, 256>>>(h, s);
        gemm2_kernel<0><<<dim3(RDIM / 128, SEQ / 128), 128>>>(
            s, rW + (size_t)i * RDIM * RDIM, rb + i * RDIM, h, SEQ, RDIM, RDIM);
    }
    srms_relu_kernel<<<SEQ, 256>>>(h, s);
    gemm2_kernel<0><<<dim3(DD1 / 128, SEQ / 128), 128>>>(
        s, rWout, rbout, cf, SEQ, DD1, RDIM);
    coeff_scale_transpose<<<(SEQ * DD1 + 255) / 256, 256>>>(cf, aT);

    // ---- u = silu(x@Wu+bu) via HMMA split ----
    wsplit_t_kernel<<<dim3(DD1 / 32, EMB / 32), dim3(32, 8)>>>(Wu, wthi, wtlo, EMB, DD1);
    gemm_mma_kernel<1><<<dim3(DD1 / 128, MROWS / 128), 256, MM_SMEM>>>(
        xhi, xlo, wthi, wtlo, bu, u, MROWS, DD1, EMB);

    // ---- v = silu(x@Wv+bv) ----
    wsplit_t_kernel<<<dim3(DD1 / 32, EMB / 32), dim3(32, 8)>>>(Wv, wthi, wtlo, EMB, DD1);
    gemm_mma_kernel<1><<<dim3(DD1 / 128, MROWS / 128), 256, MM_SMEM>>>(
        xhi, xlo, wthi, wtlo, bv, v, MROWS, DD1, EMB);

    // ---- causal conv ----
    transpose_v_kernel<<<dim3(SEQ / 32, DD1 / 32, BATCH), dim3(32, 8)>>>(v, vT);
    conv3_kernel<<<dim3(SEQ / 512, DD1), 128>>>(vT, aT, v /* reuse as convT */);
    transpose_back_kernel<<<dim3(DD1 / 32, SEQ / 32, BATCH), dim3(32, 8)>>>(v, cv);

    // ---- gate + split, then out = g @ Wo + bo ----
    gate_split_kernel<<<(MROWS * DD1 / 4 + 255) / 256, 256>>>(u, cv, ghi, glo, MROWS * DD1);
    wsplit_t_kernel<<<dim3(EMB / 32, DD1 / 32), dim3(32, 8)>>>(Wo, wthi, wtlo, DD1, EMB);
    gemm_mma_kernel<0><<<dim3(EMB / 128, MROWS / 128), 256, MM_SMEM>>>(
        ghi, glo, wthi, wtlo, bo, out, MROWS, EMB, DD1);
}

// round 14
// speedup vs baseline: 2.1351x; 1.4386x over previous
#include <cuda_runtime.h>
#include <cuda_bf16.h>
#include <math.h>

typedef unsigned long long ull;
typedef unsigned int u32;
typedef unsigned short u16;

#define BATCH 8
#define SEQ   2048
#define EMB   512
#define DD1   1536
#define RDIM  512
#define MROWS (BATCH*SEQ)      // 16384
#define GAMMA_F 0.99f
#define PD_LEN 2176

// ---- device-global scratch ----
__device__ float g_u[MROWS*DD1];
__device__ float g_vbuf[MROWS*DD1];   // v (M,D1)
__device__ float g_vT[MROWS*DD1];     // convT (B,D1,N)
__device__ float g_conv[MROWS*DD1];   // conv (M,D1)
__device__ float g_h[SEQ*RDIM];
__device__ float g_s[SEQ*RDIM];
__device__ float g_coeffs[SEQ*DD1];
__device__ float g_acoefT[DD1*SEQ];
// bf16 splits
__device__ u16 g_xhi[MROWS*EMB];
__device__ u16 g_xlo[MROWS*EMB];
__device__ u16 g_ghi[MROWS*DD1];      // also reused (cast u32) as packed v-pairs hi
__device__ u16 g_glo[MROWS*DD1];      // also reused (cast u32) as packed v-pairs lo
__device__ u16 g_wthi[DD1*EMB];
__device__ u16 g_wtlo[DD1*EMB];
// packed coefficient pairs: pd[c][slot] = {a[t-1]<<16 | a[t]}, slot = t+128
__device__ u32 g_pdhi[DD1*PD_LEN];
__device__ u32 g_pdlo[DD1*PD_LEN];

// ---------------- f32x2 helpers ----------------
__device__ __forceinline__ void ffma2(ull &d, ull a, ull b) {
    asm("fma.rn.f32x2 %0, %1, %2, %0;" : "+l"(d) : "l"(a), "l"(b));
}
__device__ __forceinline__ ull pack2(float lo, float hi) {
    ull r; asm("mov.b64 %0, {%1, %2};" : "=l"(r) : "f"(lo), "f"(hi)); return r;
}
__device__ __forceinline__ void unpack2(ull v, float &lo, float &hi) {
    asm("mov.b64 {%0, %1}, %2;" : "=f"(lo), "=f"(hi) : "l"(v));
}
__device__ __forceinline__ u32 smem_u32(const void* p) {
    u32 a; asm("{ .reg .u64 t; cvta.to.shared.u64 t, %1; cvt.u32.u64 %0, t; }"
               : "=r"(a) : "l"(p));
    return a;
}

// ---------------- mma.sync / ldmatrix / cp.async ----------------
__device__ __forceinline__ void mma_bf16(float* c, const u32* a, const u32* b) {
    asm volatile("mma.sync.aligned.m16n8k16.row.col.f32.bf16.bf16.f32 "
        "{%0,%1,%2,%3}, {%4,%5,%6,%7}, {%8,%9}, {%0,%1,%2,%3};"
        : "+f"(c[0]), "+f"(c[1]), "+f"(c[2]), "+f"(c[3])
        : "r"(a[0]), "r"(a[1]), "r"(a[2]), "r"(a[3]), "r"(b[0]), "r"(b[1]));
}
__device__ __forceinline__ void ldsm4(u32* r, u32 addr) {
    asm volatile("ldmatrix.sync.aligned.m8n8.x4.shared.b16 {%0,%1,%2,%3}, [%4];"
        : "=r"(r[0]), "=r"(r[1]), "=r"(r[2]), "=r"(r[3]) : "r"(addr));
}
__device__ __forceinline__ void cp16(u32 saddr, const void* g) {
    asm volatile("cp.async.cg.shared.global [%0], [%1], 16;" :: "r"(saddr), "l"(g));
}
__device__ __forceinline__ void cp_commit() { asm volatile("cp.async.commit_group;" ::: "memory"); }
__device__ __forceinline__ void cp_wait0()  { asm volatile("cp.async.wait_group 0;" ::: "memory"); }

// ---------------- RPE init ----------------
__global__ void rpe_init_kernel(const float* __restrict__ Win,
                                const float* __restrict__ bin,
                                float* __restrict__ h) {
    int g = blockIdx.x * blockDim.x + threadIdx.x;
    if (g >= SEQ * RDIM) return;
    int n = g >> 9, r = g & 511;
    h[g] = (float)n * Win[r] + bin[r];
}

// --------- srms + relu rows of 512 ---------
__global__ void srms_relu_kernel(const float* __restrict__ in,
                                 float* __restrict__ out) {
    int row = blockIdx.x;
    const float* p = in + (size_t)row * RDIM;
    int tid = threadIdx.x;
    float v0 = p[tid], v1 = p[tid + 256];
    float ss = v0 * v0 + v1 * v1;
    #pragma unroll
    for (int o = 16; o > 0; o >>= 1) ss += __shfl_xor_sync(0xffffffffu, ss, o);
    __shared__ float ws[8];
    if ((tid & 31) == 0) ws[tid >> 5] = ss;
    __syncthreads();
    float tot = 0.f;
    #pragma unroll
    for (int i = 0; i < 8; ++i) tot += ws[i];
    float scale = 1.f / (sqrtf(tot * (1.f / (float)RDIM)) + 1e-6f);
    out[(size_t)row * RDIM + tid]       = fmaxf(v0 * scale, 0.f);
    out[(size_t)row * RDIM + tid + 256] = fmaxf(v1 * scale, 0.f);
}

// ---------------- f32x2 SGEMM (RPE only) ----------------
template<int ACT>
__global__ __launch_bounds__(128)
void gemm2_kernel(const float* __restrict__ A, const float* __restrict__ B,
                  const float* __restrict__ bias, float* __restrict__ C,
                  int M, int N, int K)
{
    __shared__ __align__(16) float As[2][8][128];
    __shared__ __align__(16) float Bs[2][8][128];
    const int tid  = threadIdx.x;
    const int row0 = blockIdx.y * 128, col0 = blockIdx.x * 128;
    const int rbase = (tid >> 4) * 16;
    const int c1 = (tid & 15) * 4, c2 = c1 + 64;
    const float* Ap = A + (size_t)(row0 + tid) * K;
    const int brow = tid >> 4, bc = (tid & 15) * 4;
    const float* Bp = B + (size_t)brow * N + col0 + bc;
    ull acc[8][8];
    #pragma unroll
    for (int i = 0; i < 8; ++i)
        #pragma unroll
        for (int j = 0; j < 8; ++j) acc[i][j] = 0ull;
    const int nk = K >> 3;
    float4 ra0, ra1, rb0, rb1;
    ra0 = *(const float4*)Ap; ra1 = *(const float4*)(Ap + 4);
    rb0 = *(const float4*)Bp; rb1 = *(const float4*)(Bp + 64);
    As[0][0][tid]=ra0.x; As[0][1][tid]=ra0.y; As[0][2][tid]=ra0.z; As[0][3][tid]=ra0.w;
    As[0][4][tid]=ra1.x; As[0][5][tid]=ra1.y; As[0][6][tid]=ra1.z; As[0][7][tid]=ra1.w;
    *(float4*)&Bs[0][brow][bc] = rb0; *(float4*)&Bs[0][brow][bc+64] = rb1;
    __syncthreads();
    int cur = 0;
    for (int kt = 0; kt < nk; ++kt) {
        const bool has = (kt + 1 < nk);
        if (has) {
            Ap += 8; Bp += (size_t)8 * N;
            ra0 = *(const float4*)Ap; ra1 = *(const float4*)(Ap + 4);
            rb0 = *(const float4*)Bp; rb1 = *(const float4*)(Bp + 64);
        }
        #pragma unroll
        for (int k = 0; k < 8; ++k) {
            union { float4 f; ull u[2]; } q0, q1, q2, q3;
            q0.f = *(const float4*)&As[cur][k][rbase];
            q1.f = *(const float4*)&As[cur][k][rbase + 4];
            q2.f = *(const float4*)&As[cur][k][rbase + 8];
            q3.f = *(const float4*)&As[cur][k][rbase + 12];
            ull ar[8] = { q0.u[0],q0.u[1],q1.u[0],q1.u[1],q2.u[0],q2.u[1],q3.u[0],q3.u[1] };
            float4 b0 = *(const float4*)&Bs[cur][k][c1];
            float4 b1 = *(const float4*)&Bs[cur][k][c2];
            ull bs[8] = { pack2(b0.x,b0.x),pack2(b0.y,b0.y),pack2(b0.z,b0.z),pack2(b0.w,b0.w),
                          pack2(b1.x,b1.x),pack2(b1.y,b1.y),pack2(b1.z,b1.z),pack2(b1.w,b1.w) };
            #pragma unroll
            for (int i = 0; i < 8; ++i)
                #pragma unroll
                for (int j = 0; j < 8; ++j) ffma2(acc[i][j], ar[i], bs[j]);
        }
        if (has) {
            const int nxt = cur ^ 1;
            As[nxt][0][tid]=ra0.x; As[nxt][1][tid]=ra0.y; As[nxt][2][tid]=ra0.z; As[nxt][3][tid]=ra0.w;
            As[nxt][4][tid]=ra1.x; As[nxt][5][tid]=ra1.y; As[nxt][6][tid]=ra1.z; As[nxt][7][tid]=ra1.w;
            *(float4*)&Bs[nxt][brow][bc] = rb0; *(float4*)&Bs[nxt][brow][bc+64] = rb1;
        }
        __syncthreads();
        cur ^= 1;
    }
    float4 bb1 = *(const float4*)&bias[col0 + c1];
    float4 bb2 = *(const float4*)&bias[col0 + c2];
    float bb[8] = { bb1.x,bb1.y,bb1.z,bb1.w, bb2.x,bb2.y,bb2.z,bb2.w };
    #pragma unroll
    for (int i = 0; i < 8; ++i) {
        const int r = row0 + rbase + 2 * i;
        float e[8], o[8];
        #pragma unroll
        for (int j = 0; j < 8; ++j) {
            float lo, hi; unpack2(acc[i][j], lo, hi);
            lo += bb[j]; hi += bb[j];
            if (ACT) { lo = lo/(1.f+__expf(-lo)); hi = hi/(1.f+__expf(-hi)); }
            e[j] = lo; o[j] = hi;
        }
        *(float4*)&C[(size_t)r*N + col0 + c1]     = make_float4(e[0],e[1],e[2],e[3]);
        *(float4*)&C[(size_t)(r+1)*N + col0 + c1] = make_float4(o[0],o[1],o[2],o[3]);
        *(float4*)&C[(size_t)r*N + col0 + c2]     = make_float4(e[4],e[5],e[6],e[7]);
        *(float4*)&C[(size_t)(r+1)*N + col0 + c2] = make_float4(o[4],o[5],o[6],o[7]);
    }
}

// ---- coeff decay + transpose ----
__global__ void coeff_scale_transpose(const float* __restrict__ coeffs,
                                      float* __restrict__ aT) {
    int g = blockIdx.x * blockDim.x + threadIdx.x;
    if (g >= SEQ * DD1) return;
    int t = g / DD1, c = g - t * DD1;
    float dec = (t == 0) ? 1.f : powf(GAMMA_F, (float)t);
    aT[(size_t)c * SEQ + t] = coeffs[g] * dec;
}

// ---------------- bf16 split helpers ----------------
__device__ __forceinline__ u16 bf_hi(float x) {
    __nv_bfloat16 b = __float2bfloat16(x);
    return *(u16*)&b;
}
__device__ __forceinline__ float bf_val(u16 b) {
    __nv_bfloat16 h = *(__nv_bfloat16*)&b;
    return __bfloat162float(h);
}

// ---- pack coefficient pairs: pd[c][t+128] = {bf(a[t-1])<<16 | bf(a[t])} ----
__global__ void coef_pack_kernel(const float* __restrict__ aT,
                                 u32* __restrict__ pdh, u32* __restrict__ pdl) {
    int g = blockIdx.x * blockDim.x + threadIdx.x;
    if (g >= DD1 * PD_LEN) return;
    int c = g / PD_LEN, slot = g - c * PD_LEN;
    int t = slot - 128;
    float a0 = (t >= 0 && t < SEQ) ? aT[(size_t)c * SEQ + t] : 0.f;
    float a1 = (t - 1 >= 0 && t - 1 < SEQ) ? aT[(size_t)c * SEQ + t - 1] : 0.f;
    u16 h0 = bf_hi(a0), h1 = bf_hi(a1);
    u16 l0 = bf_hi(a0 - bf_val(h0)), l1 = bf_hi(a1 - bf_val(h1));
    pdh[g] = ((u32)h1 << 16) | (u32)h0;
    pdl[g] = ((u32)l1 << 16) | (u32)l0;
}

// ---- vpack: v (B,N,D1) f32 -> paired bf16 splits (D1, 8, 1024) u32 ----
// vp[c][b][sp] = {bf(v[b,2sp+1,c])<<16 | bf(v[b,2sp,c])}
__global__ void vpack_kernel(const float* __restrict__ v,
                             u32* __restrict__ ph, u32* __restrict__ pl) {
    __shared__ float tile[64][33];
    int b = blockIdx.z, n0 = blockIdx.x << 6, c0 = blockIdx.y << 5;
    int tx = threadIdx.x, ty = threadIdx.y;   // (32,16)
    for (int r = ty; r < 64; r += 16)
        tile[r][tx] = v[((size_t)(b * SEQ) + n0 + r) * DD1 + c0 + tx];
    __syncthreads();
    #pragma unroll
    for (int cc = 0; cc < 2; ++cc) {
        int cl = ty * 2 + cc;
        float x0 = tile[tx * 2][cl], x1 = tile[tx * 2 + 1][cl];
        u16 h0 = bf_hi(x0), h1 = bf_hi(x1);
        u16 l0 = bf_hi(x0 - bf_val(h0)), l1 = bf_hi(x1 - bf_val(h1));
        size_t o = (((size_t)(c0 + cl) * 8) + b) * 1024 + (n0 >> 1) + tx;
        ph[o] = ((u32)h1 << 16) | (u32)h0;
        pl[o] = ((u32)l1 << 16) | (u32)l0;
    }
}

// ---------------- Toeplitz-HMMA causal conv ----------------
// One CTA per channel. O (2048x8 f32) lives in smem; d-outer loop reuses the
// Toeplitz A fragments across all (i, j=i-d) tile pairs. No syncs in mainloop.
#define CV_SMEM (2*PD_LEN*4 + 2*8*1028*4 + 2048*9*4)   // 156928 B

__global__ __launch_bounds__(256, 1)
void convc_kernel(const u32* __restrict__ vph, const u32* __restrict__ vpl,
                  const u32* __restrict__ pdhi, const u32* __restrict__ pdlo,
                  float* __restrict__ convT)   // (B, D1, N)
{
    extern __shared__ char cs[];
    u32* pdh = (u32*)cs;                    // [2176]
    u32* pdl = pdh + PD_LEN;                // [2176]
    u32* Vh  = pdl + PD_LEN;                // [8][1028]
    u32* Vl  = Vh + 8 * 1028;               // [8][1028]
    float* Osm = (float*)(Vl + 8 * 1028);   // [2048][9]

    const int c = blockIdx.x;
    const int tid = threadIdx.x, lane = tid & 31, wid = tid >> 5;
    const int lr = lane >> 2, q = lane & 3;
    const int mb = wid << 4;

    for (int k = tid; k < PD_LEN; k += 256) {
        pdh[k] = pdhi[(size_t)c * PD_LEN + k];
        pdl[k] = pdlo[(size_t)c * PD_LEN + k];
    }
    for (int k = tid; k < 8 * 1024; k += 256) {
        int b = k >> 10, sp = k & 1023;
        Vh[b * 1028 + sp] = vph[((size_t)c * 8 + b) * 1024 + sp];
        Vl[b * 1028 + sp] = vpl[((size_t)c * 8 + b) * 1024 + sp];
    }
    for (int k = tid; k < 2048 * 9; k += 256) Osm[k] = 0.f;
    __syncthreads();

    for (int d = 0; d < 16; ++d) {
        // Toeplitz A fragments for this diagonal, built once per warp.
        u32 Ah[8][4], Al[8][4];
        #pragma unroll
        for (int ks = 0; ks < 8; ++ks) {
            int s0 = 128 + (d << 7) + mb + lr - (ks << 4) - (q << 1);
            Ah[ks][0] = pdh[s0];     Ah[ks][1] = pdh[s0 + 8];
            Ah[ks][2] = pdh[s0 - 8]; Ah[ks][3] = Ah[ks][0];
            Al[ks][0] = pdl[s0];     Al[ks][1] = pdl[s0 + 8];
            Al[ks][2] = pdl[s0 - 8]; Al[ks][3] = Al[ks][0];
        }
        for (int i = d; i < 16; ++i) {
            const int j = i - d;
            float aH[4] = {0,0,0,0}, aM[4] = {0,0,0,0}, aL[4] = {0,0,0,0};
            const u32* vhb = &Vh[lr * 1028 + (j << 6) + q];
            const u32* vlb = &Vl[lr * 1028 + (j << 6) + q];
            #pragma unroll
            for (int ks = 0; ks < 8; ++ks) {
                u32 Bh[2] = { vhb[ks << 3], vhb[(ks << 3) + 4] };
                u32 Bl[2] = { vlb[ks << 3], vlb[(ks << 3) + 4] };
                mma_bf16(aH, Ah[ks], Bh);
                mma_bf16(aM, Ah[ks], Bl);
                mma_bf16(aL, Al[ks], Bh);
            }
            float* orow = &Osm[((i << 7) + mb + lr) * 9 + (q << 1)];
            orow[0]      += aH[0] + aM[0] + aL[0];
            orow[1]      += aH[1] + aM[1] + aL[1];
            orow[8*9]    += aH[2] + aM[2] + aL[2];
            orow[8*9+1]  += aH[3] + aM[3] + aL[3];
        }
    }
    __syncthreads();
    for (int k = tid; k < 2048 * 8; k += 256) {
        int b = k >> 11, n = k & 2047;
        convT[((size_t)(b * DD1 + c)) * SEQ + n] = Osm[n * 9 + b];
    }
}

// ---- transpose back: (B,D1,N) -> (B,N,D1) ----
__global__ void transpose_back_kernel(const float* __restrict__ ct, float* __restrict__ out) {
    __shared__ float tile[32][33];
    int b = blockIdx.z, c0 = blockIdx.x << 5, n0 = blockIdx.y << 5;
    int tx = threadIdx.x, ty = threadIdx.y;
    #pragma unroll
    for (int i = 0; i < 32; i += 8)
        tile[ty + i][tx] = ct[((size_t)(b * DD1 + c0 + ty + i)) * SEQ + n0 + tx];
    __syncthreads();
    #pragma unroll
    for (int i = 0; i < 32; i += 8)
        out[((size_t)(b * SEQ + n0 + ty + i)) * DD1 + c0 + tx] = tile[tx][ty + i];
}

// ---------------- element split kernels ----------------
__global__ void split_kernel(const float* __restrict__ x, u16* __restrict__ hi,
                             u16* __restrict__ lo, int n) {
    int g = (blockIdx.x * blockDim.x + threadIdx.x) << 2;
    if (g >= n) return;
    float4 v = *(const float4*)(x + g);
    u16 h[4], l[4];
    float vv[4] = { v.x, v.y, v.z, v.w };
    #pragma unroll
    for (int i = 0; i < 4; ++i) {
        h[i] = bf_hi(vv[i]);
        l[i] = bf_hi(vv[i] - bf_val(h[i]));
    }
    *(uint2*)&hi[g] = *(uint2*)h;
    *(uint2*)&lo[g] = *(uint2*)l;
}
__global__ void gate_split_kernel(const float* __restrict__ u, const float* __restrict__ cv,
                                  u16* __restrict__ hi, u16* __restrict__ lo, int n) {
    int g = (blockIdx.x * blockDim.x + threadIdx.x) << 2;
    if (g >= n) return;
    float4 a = *(const float4*)(u + g);
    float4 b = *(const float4*)(cv + g);
    float vv[4] = { a.x * b.x, a.y * b.y, a.z * b.z, a.w * b.w };
    u16 h[4], l[4];
    #pragma unroll
    for (int i = 0; i < 4; ++i) {
        h[i] = bf_hi(vv[i]);
        l[i] = bf_hi(vv[i] - bf_val(h[i]));
    }
    *(uint2*)&hi[g] = *(uint2*)h;
    *(uint2*)&lo[g] = *(uint2*)l;
}
// transpose W (K,N) -> Wt (N,K) with hi/lo split
__global__ void wsplit_t_kernel(const float* __restrict__ W, u16* __restrict__ hi,
                                u16* __restrict__ lo, int K, int N) {
    __shared__ float tile[32][33];
    int n0 = blockIdx.x << 5, k0 = blockIdx.y << 5;
    int tx = threadIdx.x, ty = threadIdx.y;   // (32,8)
    #pragma unroll
    for (int i = 0; i < 32; i += 8)
        tile[ty + i][tx] = W[(size_t)(k0 + ty + i) * N + n0 + tx];
    __syncthreads();
    #pragma unroll
    for (int i = 0; i < 32; i += 8) {
        float v = tile[tx][ty + i];
        size_t o = (size_t)(n0 + ty + i) * K + k0 + tx;
        u16 h = bf_hi(v);
        hi[o] = h;
        lo[o] = bf_hi(v - bf_val(h));
    }
}

// ---------------- HMMA split-GEMM (as R13, passing) ----------------
#define PITCH   72
#define TILE_B  (128*PITCH*2)
#define STAGE_B (4*TILE_B)
#define MM_SMEM (2*STAGE_B)

__device__ __forceinline__ void fill_stage(u32 st,
        const u16* __restrict__ Ah, const u16* __restrict__ Al,
        const u16* __restrict__ Bh, const u16* __restrict__ Bl,
        int row0, int col0, int K, int kc, int t) {
    const int r = t >> 1, hh = t & 1;
    const u32 so = (u32)(r * PITCH + hh * 32) * 2;
    const size_t goA = (size_t)(row0 + r) * K + (kc << 6) + hh * 32;
    const size_t goB = (size_t)(col0 + r) * K + (kc << 6) + hh * 32;
    #pragma unroll
    for (int e = 0; e < 4; ++e) {
        cp16(st + so + e*16,              Ah + goA + e*8);
        cp16(st + TILE_B + so + e*16,     Al + goA + e*8);
        cp16(st + 2*TILE_B + so + e*16,   Bh + goB + e*8);
        cp16(st + 3*TILE_B + so + e*16,   Bl + goB + e*8);
    }
}

template<int ACT>
__global__ __launch_bounds__(256, 1)
void gemm_mma_kernel(const u16* __restrict__ Ah, const u16* __restrict__ Al,
                     const u16* __restrict__ Bh, const u16* __restrict__ Bl,
                     const float* __restrict__ bias, float* __restrict__ C,
                     int M, int N, int K)
{
    extern __shared__ char dsm[];
    const u32 sb = smem_u32(dsm);
    const int tid = threadIdx.x, lane = tid & 31, wid = tid >> 5;
    const int wm = wid & 1;
    const int wn = wid >> 1;
    const int row0 = blockIdx.y * 128, col0 = blockIdx.x * 128;
    const int nkc = K >> 6;

    const int q = lane >> 3, l7 = lane & 7;
    const u32 aoff = (u32)((wm*64 + (q & 1)*8 + l7) * PITCH + (q >> 1)*8) * 2;
    const u32 boff = (u32)((wn*32 + (q >> 1)*8 + l7) * PITCH + (q & 1)*8) * 2;

    float acc[4][4][4];
    #pragma unroll
    for (int i = 0; i < 4; ++i)
        #pragma unroll
        for (int j = 0; j < 4; ++j)
            #pragma unroll
            for (int r = 0; r < 4; ++r) acc[i][j][r] = 0.f;

    fill_stage(sb, Ah, Al, Bh, Bl, row0, col0, K, 0, tid);
    cp_commit();

    for (int kc = 0; kc < nkc; ++kc) {
        cp_wait0();
        __syncthreads();
        const u32 st = sb + (kc & 1) * STAGE_B;
        if (kc + 1 < nkc) {
            fill_stage(sb + ((kc + 1) & 1) * STAGE_B, Ah, Al, Bh, Bl,
                       row0, col0, K, kc + 1, tid);
            cp_commit();
        }
        #pragma unroll
        for (int ks = 0; ks < 4; ++ks) {
            u32 ah[4][4], al[4][4], bh[2][4], bl[2][4];
            #pragma unroll
            for (int i = 0; i < 4; ++i) {
                ldsm4(ah[i], st + aoff + i*2304 + ks*32);
                ldsm4(al[i], st + TILE_B + aoff + i*2304 + ks*32);
            }
            #pragma unroll
            for (int jj = 0; jj < 2; ++jj) {
                ldsm4(bh[jj], st + 2*TILE_B + boff + jj*2304 + ks*32);
                ldsm4(bl[jj], st + 3*TILE_B + boff + jj*2304 + ks*32);
            }
            #pragma unroll
            for (int i = 0; i < 4; ++i)
                #pragma unroll
                for (int jn = 0; jn < 4; ++jn)
                    mma_bf16(acc[i][jn], ah[i], &bh[jn >> 1][(jn & 1) * 2]);
            #pragma unroll
            for (int i = 0; i < 4; ++i)
                #pragma unroll
                for (int jn = 0; jn < 4; ++jn)
                    mma_bf16(acc[i][jn], ah[i], &bl[jn >> 1][(jn & 1) * 2]);
            #pragma unroll
            for (int i = 0; i < 4; ++i)
                #pragma unroll
                for (int jn = 0; jn < 4; ++jn)
                    mma_bf16(acc[i][jn], al[i], &bh[jn >> 1][(jn & 1) * 2]);
        }
    }

    const int mrow = lane >> 2, ncol = (lane & 3) * 2;
    #pragma unroll
    for (int i = 0; i < 4; ++i) {
        const int m = row0 + wm*64 + i*16 + mrow;
        #pragma unroll
        for (int jn = 0; jn < 4; ++jn) {
            const int n = col0 + wn*32 + jn*8 + ncol;
            const float b0 = bias[n], b1 = bias[n + 1];
            float c0 = acc[i][jn][0] + b0, c1 = acc[i][jn][1] + b1;
            float c2 = acc[i][jn][2] + b0, c3 = acc[i][jn][3] + b1;
            if (ACT) {
                c0 = c0/(1.f+__expf(-c0)); c1 = c1/(1.f+__expf(-c1));
                c2 = c2/(1.f+__expf(-c2)); c3 = c3/(1.f+__expf(-c3));
            }
            *(float2*)&C[(size_t)m * N + n]       = make_float2(c0, c1);
            *(float2*)&C[(size_t)(m + 8) * N + n] = make_float2(c2, c3);
        }
    }
}

// ================================================================
extern "C" void kernel_launch(void* const* d_in, const int* in_sizes, int n_in,
                              void* d_out, int out_size) {
    const float* x     = (const float*)d_in[0];
    const float* Wu    = (const float*)d_in[1];
    const float* bu    = (const float*)d_in[2];
    const float* Wv    = (const float*)d_in[3];
    const float* bv    = (const float*)d_in[4];
    const float* Wo    = (const float*)d_in[5];
    const float* bo    = (const float*)d_in[6];
    const float* rWin  = (const float*)d_in[7];
    const float* rbin  = (const float*)d_in[8];
    const float* rW    = (const float*)d_in[9];
    const float* rb    = (const float*)d_in[10];
    const float* rWout = (const float*)d_in[11];
    const float* rbout = (const float*)d_in[12];
    float* out = (float*)d_out;

    float *u, *v, *cvT, *cv, *h, *s, *cf, *aT;
    u16 *xhi, *xlo, *ghi, *glo, *wthi, *wtlo;
    u32 *pdh, *pdl;
    cudaGetSymbolAddress((void**)&u,  g_u);
    cudaGetSymbolAddress((void**)&v,  g_vbuf);
    cudaGetSymbolAddress((void**)&cvT, g_vT);
    cudaGetSymbolAddress((void**)&cv, g_conv);
    cudaGetSymbolAddress((void**)&h,  g_h);
    cudaGetSymbolAddress((void**)&s,  g_s);
    cudaGetSymbolAddress((void**)&cf, g_coeffs);
    cudaGetSymbolAddress((void**)&aT, g_acoefT);
    cudaGetSymbolAddress((void**)&xhi, g_xhi);
    cudaGetSymbolAddress((void**)&xlo, g_xlo);
    cudaGetSymbolAddress((void**)&ghi, g_ghi);
    cudaGetSymbolAddress((void**)&glo, g_glo);
    cudaGetSymbolAddress((void**)&wthi, g_wthi);
    cudaGetSymbolAddress((void**)&wtlo, g_wtlo);
    cudaGetSymbolAddress((void**)&pdh, g_pdhi);
    cudaGetSymbolAddress((void**)&pdl, g_pdlo);
    u32* vph = (u32*)ghi;   // reuse: 8192 u32 per channel, freed before gate_split
    u32* vpl = (u32*)glo;

    cudaFuncSetAttribute(gemm_mma_kernel<0>, cudaFuncAttributeMaxDynamicSharedMemorySize, MM_SMEM);
    cudaFuncSetAttribute(gemm_mma_kernel<1>, cudaFuncAttributeMaxDynamicSharedMemorySize, MM_SMEM);
    cudaFuncSetAttribute(convc_kernel, cudaFuncAttributeMaxDynamicSharedMemorySize, CV_SMEM);

    // ---- split x into bf16 hi/lo ----
    split_kernel<<<(MROWS * EMB / 4 + 255) / 256, 256>>>(x, xhi, xlo, MROWS * EMB);

    // ---- RPE MLP (f32x2, exact) ----
    rpe_init_kernel<<<(SEQ * RDIM + 255) / 256, 256>>>(rWin, rbin, h);
    for (int i = 0; i < 3; ++i) {
        srms_relu_kernel<<<SEQ, 256>>>(h, s);
        gemm2_kernel<0><<<dim3(RDIM / 128, SEQ / 128), 128>>>(
            s, rW + (size_t)i * RDIM * RDIM, rb + i * RDIM, h, SEQ, RDIM, RDIM);
    }
    srms_relu_kernel<<<SEQ, 256>>>(h, s);
    gemm2_kernel<0><<<dim3(DD1 / 128, SEQ / 128), 128>>>(
        s, rWout, rbout, cf, SEQ, DD1, RDIM);
    coeff_scale_transpose<<<(SEQ * DD1 + 255) / 256, 256>>>(cf, aT);
    coef_pack_kernel<<<(DD1 * PD_LEN + 255) / 256, 256>>>(aT, pdh, pdl);

    // ---- u = silu(x@Wu+bu) via HMMA split ----
    wsplit_t_kernel<<<dim3(DD1 / 32, EMB / 32), dim3(32, 8)>>>(Wu, wthi, wtlo, EMB, DD1);
    gemm_mma_kernel<1><<<dim3(DD1 / 128, MROWS / 128), 256, MM_SMEM>>>(
        xhi, xlo, wthi, wtlo, bu, u, MROWS, DD1, EMB);

    // ---- v = silu(x@Wv+bv) ----
    wsplit_t_kernel<<<dim3(DD1 / 32, EMB / 32), dim3(32, 8)>>>(Wv, wthi, wtlo, EMB, DD1);
    gemm_mma_kernel<1><<<dim3(DD1 / 128, MROWS / 128), 256, MM_SMEM>>>(
        xhi, xlo, wthi, wtlo, bv, v, MROWS, DD1, EMB);

    // ---- causal conv on tensor pipe ----
    vpack_kernel<<<dim3(SEQ / 64, DD1 / 32, BATCH), dim3(32, 16)>>>(v, vph, vpl);
    convc_kernel<<<DD1, 256, CV_SMEM>>>(vph, vpl, pdh, pdl, cvT);
    transpose_back_kernel<<<dim3(DD1 / 32, SEQ / 32, BATCH), dim3(32, 8)>>>(cvT, cv);

    // ---- gate + split, then out = g @ Wo + bo ----
    gate_split_kernel<<<(MROWS * DD1 / 4 + 255) / 256, 256>>>(u, cv, ghi, glo, MROWS * DD1);
    wsplit_t_kernel<<<dim3(EMB / 32, DD1 / 32), dim3(32, 8)>>>(Wo, wthi, wtlo, DD1, EMB);
    gemm_mma_kernel<0><<<dim3(EMB / 128, MROWS / 128), 256, MM_SMEM>>>(
        ghi, glo, wthi, wtlo, bo, out, MROWS, EMB, DD1);
}

// round 15
// speedup vs baseline: 2.2707x; 1.0635x over previous
#include <cuda_runtime.h>
#include <cuda_bf16.h>
#include <math.h>

typedef unsigned long long ull;
typedef unsigned int u32;
typedef unsigned short u16;

#define BATCH 8
#define SEQ   2048
#define EMB   512
#define DD1   1536
#define RDIM  512
#define MROWS (BATCH*SEQ)      // 16384
#define GAMMA_F 0.99f
#define PD_LEN 2176

// ---- device-global scratch ----
__device__ float g_u[MROWS*DD1];
__device__ float g_vbuf[MROWS*DD1];   // v (M,D1)
__device__ float g_vT[MROWS*DD1];     // convT (B,D1,N)
__device__ float g_h[SEQ*RDIM];
__device__ float g_coeffs[SEQ*DD1];
__device__ float g_acoefT[DD1*SEQ];
// bf16 splits
__device__ u16 g_xhi[MROWS*EMB];
__device__ u16 g_xlo[MROWS*EMB];
__device__ u16 g_ghi[MROWS*DD1];      // reused: s-split -> vpack hi -> gate hi
__device__ u16 g_glo[MROWS*DD1];      // reused: s-split -> vpack lo -> gate lo
__device__ u16 g_wthi[DD1*EMB];
__device__ u16 g_wtlo[DD1*EMB];
// packed coefficient pairs: pd[c][slot] = {a[t-1]<<16 | a[t]}, slot = t+128
__device__ u32 g_pdhi[DD1*PD_LEN];
__device__ u32 g_pdlo[DD1*PD_LEN];

__device__ __forceinline__ u32 smem_u32(const void* p) {
    u32 a; asm("{ .reg .u64 t; cvta.to.shared.u64 t, %1; cvt.u32.u64 %0, t; }"
               : "=r"(a) : "l"(p));
    return a;
}

// ---------------- mma.sync / ldmatrix / cp.async ----------------
__device__ __forceinline__ void mma_bf16(float* c, const u32* a, const u32* b) {
    asm volatile("mma.sync.aligned.m16n8k16.row.col.f32.bf16.bf16.f32 "
        "{%0,%1,%2,%3}, {%4,%5,%6,%7}, {%8,%9}, {%0,%1,%2,%3};"
        : "+f"(c[0]), "+f"(c[1]), "+f"(c[2]), "+f"(c[3])
        : "r"(a[0]), "r"(a[1]), "r"(a[2]), "r"(a[3]), "r"(b[0]), "r"(b[1]));
}
__device__ __forceinline__ void ldsm4(u32* r, u32 addr) {
    asm volatile("ldmatrix.sync.aligned.m8n8.x4.shared.b16 {%0,%1,%2,%3}, [%4];"
        : "=r"(r[0]), "=r"(r[1]), "=r"(r[2]), "=r"(r[3]) : "r"(addr));
}
__device__ __forceinline__ void cp16(u32 saddr, const void* g) {
    asm volatile("cp.async.cg.shared.global [%0], [%1], 16;" :: "r"(saddr), "l"(g));
}
__device__ __forceinline__ void cp_commit() { asm volatile("cp.async.commit_group;" ::: "memory"); }
__device__ __forceinline__ void cp_wait0()  { asm volatile("cp.async.wait_group 0;" ::: "memory"); }

// ---------------- bf16 split helpers ----------------
__device__ __forceinline__ u16 bf_hi(float x) {
    __nv_bfloat16 b = __float2bfloat16(x);
    return *(u16*)&b;
}
__device__ __forceinline__ float bf_val(u16 b) {
    __nv_bfloat16 h = *(__nv_bfloat16*)&b;
    return __bfloat162float(h);
}

// ---------------- RPE init ----------------
__global__ void rpe_init_kernel(const float* __restrict__ Win,
                                const float* __restrict__ bin,
                                float* __restrict__ h) {
    int g = blockIdx.x * blockDim.x + threadIdx.x;
    if (g >= SEQ * RDIM) return;
    int n = g >> 9, r = g & 511;
    h[g] = (float)n * Win[r] + bin[r];
}

// --------- srms + relu rows of 512, emitting bf16 hi/lo split ---------
__global__ void srms_relu_split_kernel(const float* __restrict__ in,
                                       u16* __restrict__ hi, u16* __restrict__ lo) {
    int row = blockIdx.x;
    const float* p = in + (size_t)row * RDIM;
    int tid = threadIdx.x;
    float v0 = p[tid], v1 = p[tid + 256];
    float ss = v0 * v0 + v1 * v1;
    #pragma unroll
    for (int o = 16; o > 0; o >>= 1) ss += __shfl_xor_sync(0xffffffffu, ss, o);
    __shared__ float ws[8];
    if ((tid & 31) == 0) ws[tid >> 5] = ss;
    __syncthreads();
    float tot = 0.f;
    #pragma unroll
    for (int i = 0; i < 8; ++i) tot += ws[i];
    float scale = 1.f / (sqrtf(tot * (1.f / (float)RDIM)) + 1e-6f);
    float s0 = fmaxf(v0 * scale, 0.f), s1 = fmaxf(v1 * scale, 0.f);
    size_t o0 = (size_t)row * RDIM + tid;
    u16 h0 = bf_hi(s0), h1 = bf_hi(s1);
    hi[o0] = h0;        lo[o0] = bf_hi(s0 - bf_val(h0));
    hi[o0 + 256] = h1;  lo[o0 + 256] = bf_hi(s1 - bf_val(h1));
}

// ---- coeff decay + transpose (tiled, coalesced both sides) ----
__global__ void coeff_scale_transpose(const float* __restrict__ coeffs,
                                      float* __restrict__ aT) {
    __shared__ float tile[32][33];
    int t0 = blockIdx.x << 5, c0 = blockIdx.y << 5;
    int tx = threadIdx.x, ty = threadIdx.y;   // (32,8)
    #pragma unroll
    for (int i = 0; i < 32; i += 8) {
        int t = t0 + ty + i;
        tile[ty + i][tx] = coeffs[(size_t)t * DD1 + c0 + tx] * powf(GAMMA_F, (float)t);
    }
    __syncthreads();
    #pragma unroll
    for (int i = 0; i < 32; i += 8)
        aT[(size_t)(c0 + ty + i) * SEQ + t0 + tx] = tile[tx][ty + i];
}

// ---- pack coefficient pairs: pd[c][t+128] = {bf(a[t-1])<<16 | bf(a[t])} ----
__global__ void coef_pack_kernel(const float* __restrict__ aT,
                                 u32* __restrict__ pdh, u32* __restrict__ pdl) {
    int g = blockIdx.x * blockDim.x + threadIdx.x;
    if (g >= DD1 * PD_LEN) return;
    int c = g / PD_LEN, slot = g - c * PD_LEN;
    int t = slot - 128;
    float a0 = (t >= 0 && t < SEQ) ? aT[(size_t)c * SEQ + t] : 0.f;
    float a1 = (t - 1 >= 0 && t - 1 < SEQ) ? aT[(size_t)c * SEQ + t - 1] : 0.f;
    u16 h0 = bf_hi(a0), h1 = bf_hi(a1);
    u16 l0 = bf_hi(a0 - bf_val(h0)), l1 = bf_hi(a1 - bf_val(h1));
    pdh[g] = ((u32)h1 << 16) | (u32)h0;
    pdl[g] = ((u32)l1 << 16) | (u32)l0;
}

// ---- vpack: v (B,N,D1) f32 -> paired bf16 splits (D1, 8, 1024) u32 ----
__global__ void vpack_kernel(const float* __restrict__ v,
                             u32* __restrict__ ph, u32* __restrict__ pl) {
    __shared__ float tile[64][33];
    int b = blockIdx.z, n0 = blockIdx.x << 6, c0 = blockIdx.y << 5;
    int tx = threadIdx.x, ty = threadIdx.y;   // (32,16)
    for (int r = ty; r < 64; r += 16)
        tile[r][tx] = v[((size_t)(b * SEQ) + n0 + r) * DD1 + c0 + tx];
    __syncthreads();
    #pragma unroll
    for (int cc = 0; cc < 2; ++cc) {
        int cl = ty * 2 + cc;
        float x0 = tile[tx * 2][cl], x1 = tile[tx * 2 + 1][cl];
        u16 h0 = bf_hi(x0), h1 = bf_hi(x1);
        u16 l0 = bf_hi(x0 - bf_val(h0)), l1 = bf_hi(x1 - bf_val(h1));
        size_t o = (((size_t)(c0 + cl) * 8) + b) * 1024 + (n0 >> 1) + tx;
        ph[o] = ((u32)h1 << 16) | (u32)h0;
        pl[o] = ((u32)l1 << 16) | (u32)l0;
    }
}

// ---------------- Toeplitz-HMMA causal conv ----------------
#define CV_SMEM (2*PD_LEN*4 + 2*8*1028*4 + 2048*9*4)   // 156928 B

__global__ __launch_bounds__(256, 1)
void convc_kernel(const u32* __restrict__ vph, const u32* __restrict__ vpl,
                  const u32* __restrict__ pdhi, const u32* __restrict__ pdlo,
                  float* __restrict__ convT)   // (B, D1, N)
{
    extern __shared__ char cs[];
    u32* pdh = (u32*)cs;                    // [2176]
    u32* pdl = pdh + PD_LEN;                // [2176]
    u32* Vh  = pdl + PD_LEN;                // [8][1028]
    u32* Vl  = Vh + 8 * 1028;               // [8][1028]
    float* Osm = (float*)(Vl + 8 * 1028);   // [2048][9]

    const int c = blockIdx.x;
    const int tid = threadIdx.x, lane = tid & 31, wid = tid >> 5;
    const int lr = lane >> 2, q = lane & 3;
    const int mb = wid << 4;

    for (int k = tid; k < PD_LEN; k += 256) {
        pdh[k] = pdhi[(size_t)c * PD_LEN + k];
        pdl[k] = pdlo[(size_t)c * PD_LEN + k];
    }
    for (int k = tid; k < 8 * 1024; k += 256) {
        int b = k >> 10, sp = k & 1023;
        Vh[b * 1028 + sp] = vph[((size_t)c * 8 + b) * 1024 + sp];
        Vl[b * 1028 + sp] = vpl[((size_t)c * 8 + b) * 1024 + sp];
    }
    for (int k = tid; k < 2048 * 9; k += 256) Osm[k] = 0.f;
    __syncthreads();

    for (int d = 0; d < 16; ++d) {
        u32 Ah[8][4], Al[8][4];
        #pragma unroll
        for (int ks = 0; ks < 8; ++ks) {
            int s0 = 128 + (d << 7) + mb + lr - (ks << 4) - (q << 1);
            Ah[ks][0] = pdh[s0];     Ah[ks][1] = pdh[s0 + 8];
            Ah[ks][2] = pdh[s0 - 8]; Ah[ks][3] = Ah[ks][0];
            Al[ks][0] = pdl[s0];     Al[ks][1] = pdl[s0 + 8];
            Al[ks][2] = pdl[s0 - 8]; Al[ks][3] = Al[ks][0];
        }
        for (int i = d; i < 16; ++i) {
            const int j = i - d;
            float aH[4] = {0,0,0,0}, aM[4] = {0,0,0,0}, aL[4] = {0,0,0,0};
            const u32* vhb = &Vh[lr * 1028 + (j << 6) + q];
            const u32* vlb = &Vl[lr * 1028 + (j << 6) + q];
            #pragma unroll
            for (int ks = 0; ks < 8; ++ks) {
                u32 Bh[2] = { vhb[ks << 3], vhb[(ks << 3) + 4] };
                u32 Bl[2] = { vlb[ks << 3], vlb[(ks << 3) + 4] };
                mma_bf16(aH, Ah[ks], Bh);
                mma_bf16(aM, Ah[ks], Bl);
                mma_bf16(aL, Al[ks], Bh);
            }
            float* orow = &Osm[((i << 7) + mb + lr) * 9 + (q << 1)];
            orow[0]      += aH[0] + aM[0] + aL[0];
            orow[1]      += aH[1] + aM[1] + aL[1];
            orow[8*9]    += aH[2] + aM[2] + aL[2];
            orow[8*9+1]  += aH[3] + aM[3] + aL[3];
        }
    }
    __syncthreads();
    for (int k = tid; k < 2048 * 8; k += 256) {
        int b = k >> 11, n = k & 2047;
        convT[((size_t)(b * DD1 + c)) * SEQ + n] = Osm[n * 9 + b];
    }
}

// ---- fused gate + split with transposed conv read ----
// ghi/glo[(b*SEQ+n)*DD1+c] = split( u[...] * convT[b][c][n] )
__global__ void gate_split_t_kernel(const float* __restrict__ u,
                                    const float* __restrict__ convT,
                                    u16* __restrict__ hi, u16* __restrict__ lo) {
    __shared__ float tile[32][33];
    int b = blockIdx.z, c0 = blockIdx.x << 5, n0 = blockIdx.y << 5;
    int tx = threadIdx.x, ty = threadIdx.y;   // (32,8)
    #pragma unroll
    for (int i = 0; i < 32; i += 8)
        tile[ty + i][tx] = convT[((size_t)(b * DD1 + c0 + ty + i)) * SEQ + n0 + tx];
    __syncthreads();
    #pragma unroll
    for (int i = 0; i < 32; i += 8) {
        size_t off = ((size_t)(b * SEQ + n0 + ty + i)) * DD1 + c0 + tx;
        float g = u[off] * tile[tx][ty + i];
        u16 h = bf_hi(g);
        hi[off] = h;
        lo[off] = bf_hi(g - bf_val(h));
    }
}

// ---------------- element split kernels ----------------
__global__ void split_kernel(const float* __restrict__ x, u16* __restrict__ hi,
                             u16* __restrict__ lo, int n) {
    int g = (blockIdx.x * blockDim.x + threadIdx.x) << 2;
    if (g >= n) return;
    float4 v = *(const float4*)(x + g);
    u16 h[4], l[4];
    float vv[4] = { v.x, v.y, v.z, v.w };
    #pragma unroll
    for (int i = 0; i < 4; ++i) {
        h[i] = bf_hi(vv[i]);
        l[i] = bf_hi(vv[i] - bf_val(h[i]));
    }
    *(uint2*)&hi[g] = *(uint2*)h;
    *(uint2*)&lo[g] = *(uint2*)l;
}
// transpose W (K,N) -> Wt (N,K) with hi/lo split
__global__ void wsplit_t_kernel(const float* __restrict__ W, u16* __restrict__ hi,
                                u16* __restrict__ lo, int K, int N) {
    __shared__ float tile[32][33];
    int n0 = blockIdx.x << 5, k0 = blockIdx.y << 5;
    int tx = threadIdx.x, ty = threadIdx.y;   // (32,8)
    #pragma unroll
    for (int i = 0; i < 32; i += 8)
        tile[ty + i][tx] = W[(size_t)(k0 + ty + i) * N + n0 + tx];
    __syncthreads();
    #pragma unroll
    for (int i = 0; i < 32; i += 8) {
        float v = tile[tx][ty + i];
        size_t o = (size_t)(n0 + ty + i) * K + k0 + tx;
        u16 h = bf_hi(v);
        hi[o] = h;
        lo[o] = bf_hi(v - bf_val(h));
    }
}

// ---------------- HMMA split-GEMM ----------------
#define PITCH   72
#define TILE_B  (128*PITCH*2)
#define STAGE_B (4*TILE_B)
#define MM_SMEM (2*STAGE_B)

__device__ __forceinline__ void fill_stage(u32 st,
        const u16* __restrict__ Ah, const u16* __restrict__ Al,
        const u16* __restrict__ Bh, const u16* __restrict__ Bl,
        int row0, int col0, int K, int kc, int t) {
    const int r = t >> 1, hh = t & 1;
    const u32 so = (u32)(r * PITCH + hh * 32) * 2;
    const size_t goA = (size_t)(row0 + r) * K + (kc << 6) + hh * 32;
    const size_t goB = (size_t)(col0 + r) * K + (kc << 6) + hh * 32;
    #pragma unroll
    for (int e = 0; e < 4; ++e) {
        cp16(st + so + e*16,              Ah + goA + e*8);
        cp16(st + TILE_B + so + e*16,     Al + goA + e*8);
        cp16(st + 2*TILE_B + so + e*16,   Bh + goB + e*8);
        cp16(st + 3*TILE_B + so + e*16,   Bl + goB + e*8);
    }
}

template<int ACT>
__global__ __launch_bounds__(256, 1)
void gemm_mma_kernel(const u16* __restrict__ Ah, const u16* __restrict__ Al,
                     const u16* __restrict__ Bh, const u16* __restrict__ Bl,
                     const float* __restrict__ bias, float* __restrict__ C,
                     int M, int N, int K)
{
    extern __shared__ char dsm[];
    const u32 sb = smem_u32(dsm);
    const int tid = threadIdx.x, lane = tid & 31, wid = tid >> 5;
    const int wm = wid & 1;
    const int wn = wid >> 1;
    const int row0 = blockIdx.y * 128, col0 = blockIdx.x * 128;
    const int nkc = K >> 6;

    const int q = lane >> 3, l7 = lane & 7;
    const u32 aoff = (u32)((wm*64 + (q & 1)*8 + l7) * PITCH + (q >> 1)*8) * 2;
    const u32 boff = (u32)((wn*32 + (q >> 1)*8 + l7) * PITCH + (q & 1)*8) * 2;

    float acc[4][4][4];
    #pragma unroll
    for (int i = 0; i < 4; ++i)
        #pragma unroll
        for (int j = 0; j < 4; ++j)
            #pragma unroll
            for (int r = 0; r < 4; ++r) acc[i][j][r] = 0.f;

    fill_stage(sb, Ah, Al, Bh, Bl, row0, col0, K, 0, tid);
    cp_commit();

    for (int kc = 0; kc < nkc; ++kc) {
        cp_wait0();
        __syncthreads();
        const u32 st = sb + (kc & 1) * STAGE_B;
        if (kc + 1 < nkc) {
            fill_stage(sb + ((kc + 1) & 1) * STAGE_B, Ah, Al, Bh, Bl,
                       row0, col0, K, kc + 1, tid);
            cp_commit();
        }
        #pragma unroll
        for (int ks = 0; ks < 4; ++ks) {
            u32 ah[4][4], al[4][4], bh[2][4], bl[2][4];
            #pragma unroll
            for (int i = 0; i < 4; ++i) {
                ldsm4(ah[i], st + aoff + i*2304 + ks*32);
                ldsm4(al[i], st + TILE_B + aoff + i*2304 + ks*32);
            }
            #pragma unroll
            for (int jj = 0; jj < 2; ++jj) {
                ldsm4(bh[jj], st + 2*TILE_B + boff + jj*2304 + ks*32);
                ldsm4(bl[jj], st + 3*TILE_B + boff + jj*2304 + ks*32);
            }
            #pragma unroll
            for (int i = 0; i < 4; ++i)
                #pragma unroll
                for (int jn = 0; jn < 4; ++jn)
                    mma_bf16(acc[i][jn], ah[i], &bh[jn >> 1][(jn & 1) * 2]);
            #pragma unroll
            for (int i = 0; i < 4; ++i)
                #pragma unroll
                for (int jn = 0; jn < 4; ++jn)
                    mma_bf16(acc[i][jn], ah[i], &bl[jn >> 1][(jn & 1) * 2]);
            #pragma unroll
            for (int i = 0; i < 4; ++i)
                #pragma unroll
                for (int jn = 0; jn < 4; ++jn)
                    mma_bf16(acc[i][jn], al[i], &bh[jn >> 1][(jn & 1) * 2]);
        }
    }

    const int mrow = lane >> 2, ncol = (lane & 3) * 2;
    #pragma unroll
    for (int i = 0; i < 4; ++i) {
        const int m = row0 + wm*64 + i*16 + mrow;
        #pragma unroll
        for (int jn = 0; jn < 4; ++jn) {
            const int n = col0 + wn*32 + jn*8 + ncol;
            const float b0 = bias[n], b1 = bias[n + 1];
            float c0 = acc[i][jn][0] + b0, c1 = acc[i][jn][1] + b1;
            float c2 = acc[i][jn][2] + b0, c3 = acc[i][jn][3] + b1;
            if (ACT) {
                c0 = c0/(1.f+__expf(-c0)); c1 = c1/(1.f+__expf(-c1));
                c2 = c2/(1.f+__expf(-c2)); c3 = c3/(1.f+__expf(-c3));
            }
            *(float2*)&C[(size_t)m * N + n]       = make_float2(c0, c1);
            *(float2*)&C[(size_t)(m + 8) * N + n] = make_float2(c2, c3);
        }
    }
}

// ================================================================
extern "C" void kernel_launch(void* const* d_in, const int* in_sizes, int n_in,
                              void* d_out, int out_size) {
    const float* x     = (const float*)d_in[0];
    const float* Wu    = (const float*)d_in[1];
    const float* bu    = (const float*)d_in[2];
    const float* Wv    = (const float*)d_in[3];
    const float* bv    = (const float*)d_in[4];
    const float* Wo    = (const float*)d_in[5];
    const float* bo    = (const float*)d_in[6];
    const float* rWin  = (const float*)d_in[7];
    const float* rbin  = (const float*)d_in[8];
    const float* rW    = (const float*)d_in[9];
    const float* rb    = (const float*)d_in[10];
    const float* rWout = (const float*)d_in[11];
    const float* rbout = (const float*)d_in[12];
    float* out = (float*)d_out;

    float *u, *v, *cvT, *h, *cf, *aT;
    u16 *xhi, *xlo, *ghi, *glo, *wthi, *wtlo;
    u32 *pdh, *pdl;
    cudaGetSymbolAddress((void**)&u,  g_u);
    cudaGetSymbolAddress((void**)&v,  g_vbuf);
    cudaGetSymbolAddress((void**)&cvT, g_vT);
    cudaGetSymbolAddress((void**)&h,  g_h);
    cudaGetSymbolAddress((void**)&cf, g_coeffs);
    cudaGetSymbolAddress((void**)&aT, g_acoefT);
    cudaGetSymbolAddress((void**)&xhi, g_xhi);
    cudaGetSymbolAddress((void**)&xlo, g_xlo);
    cudaGetSymbolAddress((void**)&ghi, g_ghi);
    cudaGetSymbolAddress((void**)&glo, g_glo);
    cudaGetSymbolAddress((void**)&wthi, g_wthi);
    cudaGetSymbolAddress((void**)&wtlo, g_wtlo);
    cudaGetSymbolAddress((void**)&pdh, g_pdhi);
    cudaGetSymbolAddress((void**)&pdl, g_pdlo);
    u16* shi = ghi;          // RPE s-split (reused buffer)
    u16* slo = glo;
    u32* vph = (u32*)ghi;    // later: packed v-pairs
    u32* vpl = (u32*)glo;

    cudaFuncSetAttribute(gemm_mma_kernel<0>, cudaFuncAttributeMaxDynamicSharedMemorySize, MM_SMEM);
    cudaFuncSetAttribute(gemm_mma_kernel<1>, cudaFuncAttributeMaxDynamicSharedMemorySize, MM_SMEM);
    cudaFuncSetAttribute(convc_kernel, cudaFuncAttributeMaxDynamicSharedMemorySize, CV_SMEM);

    // ---- split x into bf16 hi/lo ----
    split_kernel<<<(MROWS * EMB / 4 + 255) / 256, 256>>>(x, xhi, xlo, MROWS * EMB);

    // ---- RPE MLP (split-HMMA) ----
    rpe_init_kernel<<<(SEQ * RDIM + 255) / 256, 256>>>(rWin, rbin, h);
    for (int i = 0; i < 3; ++i) {
        srms_relu_split_kernel<<<SEQ, 256>>>(h, shi, slo);
        wsplit_t_kernel<<<dim3(RDIM / 32, RDIM / 32), dim3(32, 8)>>>(
            rW + (size_t)i * RDIM * RDIM, wthi, wtlo, RDIM, RDIM);
        gemm_mma_kernel<0><<<dim3(RDIM / 128, SEQ / 128), 256, MM_SMEM>>>(
            shi, slo, wthi, wtlo, rb + i * RDIM, h, SEQ, RDIM, RDIM);
    }
    srms_relu_split_kernel<<<SEQ, 256>>>(h, shi, slo);
    wsplit_t_kernel<<<dim3(DD1 / 32, RDIM / 32), dim3(32, 8)>>>(rWout, wthi, wtlo, RDIM, DD1);
    gemm_mma_kernel<0><<<dim3(DD1 / 128, SEQ / 128), 256, MM_SMEM>>>(
        shi, slo, wthi, wtlo, rbout, cf, SEQ, DD1, RDIM);
    coeff_scale_transpose<<<dim3(SEQ / 32, DD1 / 32), dim3(32, 8)>>>(cf, aT);
    coef_pack_kernel<<<(DD1 * PD_LEN + 255) / 256, 256>>>(aT, pdh, pdl);

    // ---- u = silu(x@Wu+bu) via HMMA split ----
    wsplit_t_kernel<<<dim3(DD1 / 32, EMB / 32), dim3(32, 8)>>>(Wu, wthi, wtlo, EMB, DD1);
    gemm_mma_kernel<1><<<dim3(DD1 / 128, MROWS / 128), 256, MM_SMEM>>>(
        xhi, xlo, wthi, wtlo, bu, u, MROWS, DD1, EMB);

    // ---- v = silu(x@Wv+bv) ----
    wsplit_t_kernel<<<dim3(DD1 / 32, EMB / 32), dim3(32, 8)>>>(Wv, wthi, wtlo, EMB, DD1);
    gemm_mma_kernel<1><<<dim3(DD1 / 128, MROWS / 128), 256, MM_SMEM>>>(
        xhi, xlo, wthi, wtlo, bv, v, MROWS, DD1, EMB);

    // ---- causal conv on tensor pipe ----
    vpack_kernel<<<dim3(SEQ / 64, DD1 / 32, BATCH), dim3(32, 16)>>>(v, vph, vpl);
    convc_kernel<<<DD1, 256, CV_SMEM>>>(vph, vpl, pdh, pdl, cvT);

    // ---- fused gate + split (transposed conv read) ----
    gate_split_t_kernel<<<dim3(DD1 / 32, SEQ / 32, BATCH), dim3(32, 8)>>>(u, cvT, ghi, glo);

    // ---- out = g @ Wo + bo ----
    wsplit_t_kernel<<<dim3(EMB / 32, DD1 / 32), dim3(32, 8)>>>(Wo, wthi, wtlo, DD1, EMB);
    gemm_mma_kernel<0><<<dim3(EMB / 128, MROWS / 128), 256, MM_SMEM>>>(
        ghi, glo, wthi, wtlo, bo, out, MROWS, EMB, DD1);
}

// round 16
// speedup vs baseline: 2.3423x; 1.0316x over previous
#include <cuda_runtime.h>
#include <cuda_bf16.h>
#include <math.h>

typedef unsigned long long ull;
typedef unsigned int u32;
typedef unsigned short u16;

#define BATCH 8
#define SEQ   2048
#define EMB   512
#define DD1   1536
#define RDIM  512
#define MROWS (BATCH*SEQ)      // 16384
#define GAMMA_F 0.99f
#define PD_LEN 2176

// ---- device-global scratch ----
__device__ float g_u[MROWS*DD1];
__device__ float g_vbuf[MROWS*DD1];   // v (M,D1)
__device__ float g_vT[MROWS*DD1];     // convT (B,D1,N)
__device__ float g_h[SEQ*RDIM];
__device__ float g_coeffs[SEQ*DD1];
__device__ float g_acoefT[DD1*SEQ];
// bf16 splits (main path)
__device__ u16 g_xhi[MROWS*EMB];
__device__ u16 g_xlo[MROWS*EMB];
__device__ u16 g_ghi[MROWS*DD1];      // reused: vpack hi -> gate hi
__device__ u16 g_glo[MROWS*DD1];      // reused: vpack lo -> gate lo
__device__ u16 g_wthi[DD1*EMB];
__device__ u16 g_wtlo[DD1*EMB];
// RPE-private buffers (parallel stream -- must not alias main-path buffers)
__device__ u16 g_shi[SEQ*RDIM];
__device__ u16 g_slo[SEQ*RDIM];
__device__ u16 g_rwhi[DD1*RDIM];
__device__ u16 g_rwlo[DD1*RDIM];
// packed coefficient pairs: pd[c][slot] = {a[t-1]<<16 | a[t]}, slot = t+128
__device__ u32 g_pdhi[DD1*PD_LEN];
__device__ u32 g_pdlo[DD1*PD_LEN];

__device__ __forceinline__ u32 smem_u32(const void* p) {
    u32 a; asm("{ .reg .u64 t; cvta.to.shared.u64 t, %1; cvt.u32.u64 %0, t; }"
               : "=r"(a) : "l"(p));
    return a;
}

// ---------------- mma.sync / ldmatrix / cp.async ----------------
__device__ __forceinline__ void mma_bf16(float* c, const u32* a, const u32* b) {
    asm volatile("mma.sync.aligned.m16n8k16.row.col.f32.bf16.bf16.f32 "
        "{%0,%1,%2,%3}, {%4,%5,%6,%7}, {%8,%9}, {%0,%1,%2,%3};"
        : "+f"(c[0]), "+f"(c[1]), "+f"(c[2]), "+f"(c[3])
        : "r"(a[0]), "r"(a[1]), "r"(a[2]), "r"(a[3]), "r"(b[0]), "r"(b[1]));
}
__device__ __forceinline__ void ldsm4(u32* r, u32 addr) {
    asm volatile("ldmatrix.sync.aligned.m8n8.x4.shared.b16 {%0,%1,%2,%3}, [%4];"
        : "=r"(r[0]), "=r"(r[1]), "=r"(r[2]), "=r"(r[3]) : "r"(addr));
}
__device__ __forceinline__ void cp16(u32 saddr, const void* g) {
    asm volatile("cp.async.cg.shared.global [%0], [%1], 16;" :: "r"(saddr), "l"(g));
}
__device__ __forceinline__ void cp_commit() { asm volatile("cp.async.commit_group;" ::: "memory"); }
__device__ __forceinline__ void cp_wait0()  { asm volatile("cp.async.wait_group 0;" ::: "memory"); }

// ---------------- bf16 split helpers ----------------
__device__ __forceinline__ u16 bf_hi(float x) {
    __nv_bfloat16 b = __float2bfloat16(x);
    return *(u16*)&b;
}
__device__ __forceinline__ float bf_val(u16 b) {
    __nv_bfloat16 h = *(__nv_bfloat16*)&b;
    return __bfloat162float(h);
}

// ---------------- RPE init ----------------
__global__ void rpe_init_kernel(const float* __restrict__ Win,
                                const float* __restrict__ bin,
                                float* __restrict__ h) {
    int g = blockIdx.x * blockDim.x + threadIdx.x;
    if (g >= SEQ * RDIM) return;
    int n = g >> 9, r = g & 511;
    h[g] = (float)n * Win[r] + bin[r];
}

// --------- srms + relu rows of 512, emitting bf16 hi/lo split ---------
__global__ void srms_relu_split_kernel(const float* __restrict__ in,
                                       u16* __restrict__ hi, u16* __restrict__ lo) {
    int row = blockIdx.x;
    const float* p = in + (size_t)row * RDIM;
    int tid = threadIdx.x;
    float v0 = p[tid], v1 = p[tid + 256];
    float ss = v0 * v0 + v1 * v1;
    #pragma unroll
    for (int o = 16; o > 0; o >>= 1) ss += __shfl_xor_sync(0xffffffffu, ss, o);
    __shared__ float ws[8];
    if ((tid & 31) == 0) ws[tid >> 5] = ss;
    __syncthreads();
    float tot = 0.f;
    #pragma unroll
    for (int i = 0; i < 8; ++i) tot += ws[i];
    float scale = 1.f / (sqrtf(tot * (1.f / (float)RDIM)) + 1e-6f);
    float s0 = fmaxf(v0 * scale, 0.f), s1 = fmaxf(v1 * scale, 0.f);
    size_t o0 = (size_t)row * RDIM + tid;
    u16 h0 = bf_hi(s0), h1 = bf_hi(s1);
    hi[o0] = h0;        lo[o0] = bf_hi(s0 - bf_val(h0));
    hi[o0 + 256] = h1;  lo[o0 + 256] = bf_hi(s1 - bf_val(h1));
}

// ---- coeff decay + transpose (tiled, coalesced both sides) ----
__global__ void coeff_scale_transpose(const float* __restrict__ coeffs,
                                      float* __restrict__ aT) {
    __shared__ float tile[32][33];
    int t0 = blockIdx.x << 5, c0 = blockIdx.y << 5;
    int tx = threadIdx.x, ty = threadIdx.y;   // (32,8)
    #pragma unroll
    for (int i = 0; i < 32; i += 8) {
        int t = t0 + ty + i;
        tile[ty + i][tx] = coeffs[(size_t)t * DD1 + c0 + tx] * powf(GAMMA_F, (float)t);
    }
    __syncthreads();
    #pragma unroll
    for (int i = 0; i < 32; i += 8)
        aT[(size_t)(c0 + ty + i) * SEQ + t0 + tx] = tile[tx][ty + i];
}

// ---- pack coefficient pairs: pd[c][t+128] = {bf(a[t-1])<<16 | bf(a[t])} ----
__global__ void coef_pack_kernel(const float* __restrict__ aT,
                                 u32* __restrict__ pdh, u32* __restrict__ pdl) {
    int g = blockIdx.x * blockDim.x + threadIdx.x;
    if (g >= DD1 * PD_LEN) return;
    int c = g / PD_LEN, slot = g - c * PD_LEN;
    int t = slot - 128;
    float a0 = (t >= 0 && t < SEQ) ? aT[(size_t)c * SEQ + t] : 0.f;
    float a1 = (t - 1 >= 0 && t - 1 < SEQ) ? aT[(size_t)c * SEQ + t - 1] : 0.f;
    u16 h0 = bf_hi(a0), h1 = bf_hi(a1);
    u16 l0 = bf_hi(a0 - bf_val(h0)), l1 = bf_hi(a1 - bf_val(h1));
    pdh[g] = ((u32)h1 << 16) | (u32)h0;
    pdl[g] = ((u32)l1 << 16) | (u32)l0;
}

// ---- vpack: v (B,N,D1) f32 -> paired bf16 splits (D1, 8, 1024) u32 ----
__global__ void vpack_kernel(const float* __restrict__ v,
                             u32* __restrict__ ph, u32* __restrict__ pl) {
    __shared__ float tile[64][33];
    int b = blockIdx.z, n0 = blockIdx.x << 6, c0 = blockIdx.y << 5;
    int tx = threadIdx.x, ty = threadIdx.y;   // (32,16)
    for (int r = ty; r < 64; r += 16)
        tile[r][tx] = v[((size_t)(b * SEQ) + n0 + r) * DD1 + c0 + tx];
    __syncthreads();
    #pragma unroll
    for (int cc = 0; cc < 2; ++cc) {
        int cl = ty * 2 + cc;
        float x0 = tile[tx * 2][cl], x1 = tile[tx * 2 + 1][cl];
        u16 h0 = bf_hi(x0), h1 = bf_hi(x1);
        u16 l0 = bf_hi(x0 - bf_val(h0)), l1 = bf_hi(x1 - bf_val(h1));
        size_t o = (((size_t)(c0 + cl) * 8) + b) * 1024 + (n0 >> 1) + tx;
        ph[o] = ((u32)h1 << 16) | (u32)h0;
        pl[o] = ((u32)l1 << 16) | (u32)l0;
    }
}

// ---------------- Toeplitz-HMMA causal conv (6 MMA chains) ----------------
#define CV_SMEM (2*PD_LEN*4 + 2*8*1028*4 + 2048*9*4)   // 156928 B

__global__ __launch_bounds__(256, 1)
void convc_kernel(const u32* __restrict__ vph, const u32* __restrict__ vpl,
                  const u32* __restrict__ pdhi, const u32* __restrict__ pdlo,
                  float* __restrict__ convT)   // (B, D1, N)
{
    extern __shared__ char cs[];
    u32* pdh = (u32*)cs;                    // [2176]
    u32* pdl = pdh + PD_LEN;                // [2176]
    u32* Vh  = pdl + PD_LEN;                // [8][1028]
    u32* Vl  = Vh + 8 * 1028;               // [8][1028]
    float* Osm = (float*)(Vl + 8 * 1028);   // [2048][9]

    const int c = blockIdx.x;
    const int tid = threadIdx.x, lane = tid & 31, wid = tid >> 5;
    const int lr = lane >> 2, q = lane & 3;
    const int mb = wid << 4;

    for (int k = tid; k < PD_LEN; k += 256) {
        pdh[k] = pdhi[(size_t)c * PD_LEN + k];
        pdl[k] = pdlo[(size_t)c * PD_LEN + k];
    }
    for (int k = tid; k < 8 * 1024; k += 256) {
        int b = k >> 10, sp = k & 1023;
        Vh[b * 1028 + sp] = vph[((size_t)c * 8 + b) * 1024 + sp];
        Vl[b * 1028 + sp] = vpl[((size_t)c * 8 + b) * 1024 + sp];
    }
    for (int k = tid; k < 2048 * 9; k += 256) Osm[k] = 0.f;
    __syncthreads();

    for (int d = 0; d < 16; ++d) {
        u32 Ah[8][4], Al[8][4];
        #pragma unroll
        for (int ks = 0; ks < 8; ++ks) {
            int s0 = 128 + (d << 7) + mb + lr - (ks << 4) - (q << 1);
            Ah[ks][0] = pdh[s0];     Ah[ks][1] = pdh[s0 + 8];
            Ah[ks][2] = pdh[s0 - 8]; Ah[ks][3] = Ah[ks][0];
            Al[ks][0] = pdl[s0];     Al[ks][1] = pdl[s0 + 8];
            Al[ks][2] = pdl[s0 - 8]; Al[ks][3] = Al[ks][0];
        }
        for (int i = d; i < 16; ++i) {
            const int j = i - d;
            float aH0[4] = {0,0,0,0}, aM0[4] = {0,0,0,0}, aL0[4] = {0,0,0,0};
            float aH1[4] = {0,0,0,0}, aM1[4] = {0,0,0,0}, aL1[4] = {0,0,0,0};
            const u32* vhb = &Vh[lr * 1028 + (j << 6) + q];
            const u32* vlb = &Vl[lr * 1028 + (j << 6) + q];
            #pragma unroll
            for (int ks = 0; ks < 4; ++ks) {
                u32 Bh0[2] = { vhb[ks << 3], vhb[(ks << 3) + 4] };
                u32 Bl0[2] = { vlb[ks << 3], vlb[(ks << 3) + 4] };
                int k2 = ks + 4;
                u32 Bh1[2] = { vhb[k2 << 3], vhb[(k2 << 3) + 4] };
                u32 Bl1[2] = { vlb[k2 << 3], vlb[(k2 << 3) + 4] };
                mma_bf16(aH0, Ah[ks], Bh0);
                mma_bf16(aH1, Ah[k2], Bh1);
                mma_bf16(aM0, Ah[ks], Bl0);
                mma_bf16(aM1, Ah[k2], Bl1);
                mma_bf16(aL0, Al[ks], Bh0);
                mma_bf16(aL1, Al[k2], Bh1);
            }
            float* orow = &Osm[((i << 7) + mb + lr) * 9 + (q << 1)];
            orow[0]      += (aH0[0]+aH1[0]) + (aM0[0]+aM1[0]) + (aL0[0]+aL1[0]);
            orow[1]      += (aH0[1]+aH1[1]) + (aM0[1]+aM1[1]) + (aL0[1]+aL1[1]);
            orow[8*9]    += (aH0[2]+aH1[2]) + (aM0[2]+aM1[2]) + (aL0[2]+aL1[2]);
            orow[8*9+1]  += (aH0[3]+aH1[3]) + (aM0[3]+aM1[3]) + (aL0[3]+aL1[3]);
        }
    }
    __syncthreads();
    for (int k = tid; k < 2048 * 8; k += 256) {
        int b = k >> 11, n = k & 2047;
        convT[((size_t)(b * DD1 + c)) * SEQ + n] = Osm[n * 9 + b];
    }
}

// ---- fused gate + split with transposed conv read ----
__global__ void gate_split_t_kernel(const float* __restrict__ u,
                                    const float* __restrict__ convT,
                                    u16* __restrict__ hi, u16* __restrict__ lo) {
    __shared__ float tile[32][33];
    int b = blockIdx.z, c0 = blockIdx.x << 5, n0 = blockIdx.y << 5;
    int tx = threadIdx.x, ty = threadIdx.y;   // (32,8)
    #pragma unroll
    for (int i = 0; i < 32; i += 8)
        tile[ty + i][tx] = convT[((size_t)(b * DD1 + c0 + ty + i)) * SEQ + n0 + tx];
    __syncthreads();
    #pragma unroll
    for (int i = 0; i < 32; i += 8) {
        size_t off = ((size_t)(b * SEQ + n0 + ty + i)) * DD1 + c0 + tx;
        float g = u[off] * tile[tx][ty + i];
        u16 h = bf_hi(g);
        hi[off] = h;
        lo[off] = bf_hi(g - bf_val(h));
    }
}

// ---------------- element split kernels ----------------
__global__ void split_kernel(const float* __restrict__ x, u16* __restrict__ hi,
                             u16* __restrict__ lo, int n) {
    int g = (blockIdx.x * blockDim.x + threadIdx.x) << 2;
    if (g >= n) return;
    float4 v = *(const float4*)(x + g);
    u16 h[4], l[4];
    float vv[4] = { v.x, v.y, v.z, v.w };
    #pragma unroll
    for (int i = 0; i < 4; ++i) {
        h[i] = bf_hi(vv[i]);
        l[i] = bf_hi(vv[i] - bf_val(h[i]));
    }
    *(uint2*)&hi[g] = *(uint2*)h;
    *(uint2*)&lo[g] = *(uint2*)l;
}
// transpose W (K,N) -> Wt (N,K) with hi/lo split
__global__ void wsplit_t_kernel(const float* __restrict__ W, u16* __restrict__ hi,
                                u16* __restrict__ lo, int K, int N) {
    __shared__ float tile[32][33];
    int n0 = blockIdx.x << 5, k0 = blockIdx.y << 5;
    int tx = threadIdx.x, ty = threadIdx.y;   // (32,8)
    #pragma unroll
    for (int i = 0; i < 32; i += 8)
        tile[ty + i][tx] = W[(size_t)(k0 + ty + i) * N + n0 + tx];
    __syncthreads();
    #pragma unroll
    for (int i = 0; i < 32; i += 8) {
        float v = tile[tx][ty + i];
        size_t o = (size_t)(n0 + ty + i) * K + k0 + tx;
        u16 h = bf_hi(v);
        hi[o] = h;
        lo[o] = bf_hi(v - bf_val(h));
    }
}

// ---------------- HMMA split-GEMM ----------------
#define PITCH   72
#define TILE_B  (128*PITCH*2)
#define STAGE_B (4*TILE_B)
#define MM_SMEM (2*STAGE_B)

__device__ __forceinline__ void fill_stage(u32 st,
        const u16* __restrict__ Ah, const u16* __restrict__ Al,
        const u16* __restrict__ Bh, const u16* __restrict__ Bl,
        int row0, int col0, int K, int kc, int t) {
    const int r = t >> 1, hh = t & 1;
    const u32 so = (u32)(r * PITCH + hh * 32) * 2;
    const size_t goA = (size_t)(row0 + r) * K + (kc << 6) + hh * 32;
    const size_t goB = (size_t)(col0 + r) * K + (kc << 6) + hh * 32;
    #pragma unroll
    for (int e = 0; e < 4; ++e) {
        cp16(st + so + e*16,              Ah + goA + e*8);
        cp16(st + TILE_B + so + e*16,     Al + goA + e*8);
        cp16(st + 2*TILE_B + so + e*16,   Bh + goB + e*8);
        cp16(st + 3*TILE_B + so + e*16,   Bl + goB + e*8);
    }
}

template<int ACT>
__global__ __launch_bounds__(256, 1)
void gemm_mma_kernel(const u16* __restrict__ Ah, const u16* __restrict__ Al,
                     const u16* __restrict__ Bh, const u16* __restrict__ Bl,
                     const float* __restrict__ bias, float* __restrict__ C,
                     int M, int N, int K)
{
    extern __shared__ char dsm[];
    const u32 sb = smem_u32(dsm);
    const int tid = threadIdx.x, lane = tid & 31, wid = tid >> 5;
    const int wm = wid & 1;
    const int wn = wid >> 1;
    const int row0 = blockIdx.y * 128, col0 = blockIdx.x * 128;
    const int nkc = K >> 6;

    const int q = lane >> 3, l7 = lane & 7;
    const u32 aoff = (u32)((wm*64 + (q & 1)*8 + l7) * PITCH + (q >> 1)*8) * 2;
    const u32 boff = (u32)((wn*32 + (q >> 1)*8 + l7) * PITCH + (q & 1)*8) * 2;

    float acc[4][4][4];
    #pragma unroll
    for (int i = 0; i < 4; ++i)
        #pragma unroll
        for (int j = 0; j < 4; ++j)
            #pragma unroll
            for (int r = 0; r < 4; ++r) acc[i][j][r] = 0.f;

    fill_stage(sb, Ah, Al, Bh, Bl, row0, col0, K, 0, tid);
    cp_commit();

    for (int kc = 0; kc < nkc; ++kc) {
        cp_wait0();
        __syncthreads();
        const u32 st = sb + (kc & 1) * STAGE_B;
        if (kc + 1 < nkc) {
            fill_stage(sb + ((kc + 1) & 1) * STAGE_B, Ah, Al, Bh, Bl,
                       row0, col0, K, kc + 1, tid);
            cp_commit();
        }
        #pragma unroll
        for (int ks = 0; ks < 4; ++ks) {
            u32 ah[4][4], al[4][4], bh[2][4], bl[2][4];
            #pragma unroll
            for (int i = 0; i < 4; ++i) {
                ldsm4(ah[i], st + aoff + i*2304 + ks*32);
                ldsm4(al[i], st + TILE_B + aoff + i*2304 + ks*32);
            }
            #pragma unroll
            for (int jj = 0; jj < 2; ++jj) {
                ldsm4(bh[jj], st + 2*TILE_B + boff + jj*2304 + ks*32);
                ldsm4(bl[jj], st + 3*TILE_B + boff + jj*2304 + ks*32);
            }
            #pragma unroll
            for (int i = 0; i < 4; ++i)
                #pragma unroll
                for (int jn = 0; jn < 4; ++jn)
                    mma_bf16(acc[i][jn], ah[i], &bh[jn >> 1][(jn & 1) * 2]);
            #pragma unroll
            for (int i = 0; i < 4; ++i)
                #pragma unroll
                for (int jn = 0; jn < 4; ++jn)
                    mma_bf16(acc[i][jn], ah[i], &bl[jn >> 1][(jn & 1) * 2]);
            #pragma unroll
            for (int i = 0; i < 4; ++i)
                #pragma unroll
                for (int jn = 0; jn < 4; ++jn)
                    mma_bf16(acc[i][jn], al[i], &bh[jn >> 1][(jn & 1) * 2]);
        }
    }

    const int mrow = lane >> 2, ncol = (lane & 3) * 2;
    #pragma unroll
    for (int i = 0; i < 4; ++i) {
        const int m = row0 + wm*64 + i*16 + mrow;
        #pragma unroll
        for (int jn = 0; jn < 4; ++jn) {
            const int n = col0 + wn*32 + jn*8 + ncol;
            const float b0 = bias[n], b1 = bias[n + 1];
            float c0 = acc[i][jn][0] + b0, c1 = acc[i][jn][1] + b1;
            float c2 = acc[i][jn][2] + b0, c3 = acc[i][jn][3] + b1;
            if (ACT) {
                c0 = c0/(1.f+__expf(-c0)); c1 = c1/(1.f+__expf(-c1));
                c2 = c2/(1.f+__expf(-c2)); c3 = c3/(1.f+__expf(-c3));
            }
            *(float2*)&C[(size_t)m * N + n]       = make_float2(c0, c1);
            *(float2*)&C[(size_t)(m + 8) * N + n] = make_float2(c2, c3);
        }
    }
}

// ================================================================
extern "C" void kernel_launch(void* const* d_in, const int* in_sizes, int n_in,
                              void* d_out, int out_size) {
    const float* x     = (const float*)d_in[0];
    const float* Wu    = (const float*)d_in[1];
    const float* bu    = (const float*)d_in[2];
    const float* Wv    = (const float*)d_in[3];
    const float* bv    = (const float*)d_in[4];
    const float* Wo    = (const float*)d_in[5];
    const float* bo    = (const float*)d_in[6];
    const float* rWin  = (const float*)d_in[7];
    const float* rbin  = (const float*)d_in[8];
    const float* rW    = (const float*)d_in[9];
    const float* rb    = (const float*)d_in[10];
    const float* rWout = (const float*)d_in[11];
    const float* rbout = (const float*)d_in[12];
    float* out = (float*)d_out;

    float *u, *v, *cvT, *h, *cf, *aT;
    u16 *xhi, *xlo, *ghi, *glo, *wthi, *wtlo, *shi, *slo, *rwhi, *rwlo;
    u32 *pdh, *pdl;
    cudaGetSymbolAddress((void**)&u,  g_u);
    cudaGetSymbolAddress((void**)&v,  g_vbuf);
    cudaGetSymbolAddress((void**)&cvT, g_vT);
    cudaGetSymbolAddress((void**)&h,  g_h);
    cudaGetSymbolAddress((void**)&cf, g_coeffs);
    cudaGetSymbolAddress((void**)&aT, g_acoefT);
    cudaGetSymbolAddress((void**)&xhi, g_xhi);
    cudaGetSymbolAddress((void**)&xlo, g_xlo);
    cudaGetSymbolAddress((void**)&ghi, g_ghi);
    cudaGetSymbolAddress((void**)&glo, g_glo);
    cudaGetSymbolAddress((void**)&wthi, g_wthi);
    cudaGetSymbolAddress((void**)&wtlo, g_wtlo);
    cudaGetSymbolAddress((void**)&shi, g_shi);
    cudaGetSymbolAddress((void**)&slo, g_slo);
    cudaGetSymbolAddress((void**)&rwhi, g_rwhi);
    cudaGetSymbolAddress((void**)&rwlo, g_rwlo);
    cudaGetSymbolAddress((void**)&pdh, g_pdhi);
    cudaGetSymbolAddress((void**)&pdl, g_pdlo);
    u32* vph = (u32*)ghi;    // packed v-pairs (main path, before gate reuse)
    u32* vpl = (u32*)glo;

    cudaFuncSetAttribute(gemm_mma_kernel<0>, cudaFuncAttributeMaxDynamicSharedMemorySize, MM_SMEM);
    cudaFuncSetAttribute(gemm_mma_kernel<1>, cudaFuncAttributeMaxDynamicSharedMemorySize, MM_SMEM);
    cudaFuncSetAttribute(convc_kernel, cudaFuncAttributeMaxDynamicSharedMemorySize, CV_SMEM);

    // ---- fork a side stream for the RPE chain (graph-capture fork/join) ----
    cudaStream_t s2;
    cudaStreamCreate(&s2);
    cudaEvent_t eFork, eJoin;
    cudaEventCreateWithFlags(&eFork, cudaEventDisableTiming);
    cudaEventCreateWithFlags(&eJoin, cudaEventDisableTiming);
    cudaEventRecord(eFork, 0);
    cudaStreamWaitEvent(s2, eFork, 0);

    // ==== RPE chain on s2 (private buffers: h, shi/slo, rwhi/rwlo, cf, aT, pd*) ====
    rpe_init_kernel<<<(SEQ * RDIM + 255) / 256, 256, 0, s2>>>(rWin, rbin, h);
    for (int i = 0; i < 3; ++i) {
        srms_relu_split_kernel<<<SEQ, 256, 0, s2>>>(h, shi, slo);
        wsplit_t_kernel<<<dim3(RDIM / 32, RDIM / 32), dim3(32, 8), 0, s2>>>(
            rW + (size_t)i * RDIM * RDIM, rwhi, rwlo, RDIM, RDIM);
        gemm_mma_kernel<0><<<dim3(RDIM / 128, SEQ / 128), 256, MM_SMEM, s2>>>(
            shi, slo, rwhi, rwlo, rb + i * RDIM, h, SEQ, RDIM, RDIM);
    }
    srms_relu_split_kernel<<<SEQ, 256, 0, s2>>>(h, shi, slo);
    wsplit_t_kernel<<<dim3(DD1 / 32, RDIM / 32), dim3(32, 8), 0, s2>>>(
        rWout, rwhi, rwlo, RDIM, DD1);
    gemm_mma_kernel<0><<<dim3(DD1 / 128, SEQ / 128), 256, MM_SMEM, s2>>>(
        shi, slo, rwhi, rwlo, rbout, cf, SEQ, DD1, RDIM);
    coeff_scale_transpose<<<dim3(SEQ / 32, DD1 / 32), dim3(32, 8), 0, s2>>>(cf, aT);
    coef_pack_kernel<<<(DD1 * PD_LEN + 255) / 256, 256, 0, s2>>>(aT, pdh, pdl);
    cudaEventRecord(eJoin, s2);

    // ==== main stream: x split, u/v GEMMs, vpack ====
    split_kernel<<<(MROWS * EMB / 4 + 255) / 256, 256>>>(x, xhi, xlo, MROWS * EMB);

    wsplit_t_kernel<<<dim3(DD1 / 32, EMB / 32), dim3(32, 8)>>>(Wu, wthi, wtlo, EMB, DD1);
    gemm_mma_kernel<1><<<dim3(DD1 / 128, MROWS / 128), 256, MM_SMEM>>>(
        xhi, xlo, wthi, wtlo, bu, u, MROWS, DD1, EMB);

    wsplit_t_kernel<<<dim3(DD1 / 32, EMB / 32), dim3(32, 8)>>>(Wv, wthi, wtlo, EMB, DD1);
    gemm_mma_kernel<1><<<dim3(DD1 / 128, MROWS / 128), 256, MM_SMEM>>>(
        xhi, xlo, wthi, wtlo, bv, v, MROWS, DD1, EMB);

    vpack_kernel<<<dim3(SEQ / 64, DD1 / 32, BATCH), dim3(32, 16)>>>(v, vph, vpl);

    // ---- join: convc needs both vpack (main) and coef_pack (s2) ----
    cudaStreamWaitEvent(0, eJoin, 0);
    convc_kernel<<<DD1, 256, CV_SMEM>>>(vph, vpl, pdh, pdl, cvT);

    // ---- fused gate + split (transposed conv read) ----
    gate_split_t_kernel<<<dim3(DD1 / 32, SEQ / 32, BATCH), dim3(32, 8)>>>(u, cvT, ghi, glo);

    // ---- out = g @ Wo + bo ----
    wsplit_t_kernel<<<dim3(EMB / 32, DD1 / 32), dim3(32, 8)>>>(Wo, wthi, wtlo, DD1, EMB);
    gemm_mma_kernel<0><<<dim3(EMB / 128, MROWS / 128), 256, MM_SMEM>>>(
        ghi, glo, wthi, wtlo, bo, out, MROWS, EMB, DD1);
}

// round 17
// speedup vs baseline: 2.6774x; 1.1431x over previous
#include <cuda_runtime.h>
#include <cuda_bf16.h>
#include <math.h>

typedef unsigned long long ull;
typedef unsigned int u32;
typedef unsigned short u16;

#define BATCH 8
#define SEQ   2048
#define EMB   512
#define DD1   1536
#define RDIM  512
#define MROWS (BATCH*SEQ)      // 16384
#define GAMMA_F 0.99f
#define PD_LEN 2176

// ---- device-global scratch ----
__device__ float g_u[MROWS*DD1];
__device__ float g_vbuf[MROWS*DD1];   // v (M,D1)
__device__ float g_vT[MROWS*DD1];     // convT (B,D1,N)
__device__ float g_h[SEQ*RDIM];
__device__ float g_coeffs[SEQ*DD1];
__device__ float g_acoefT[DD1*SEQ];
// bf16 splits (main path)
__device__ u16 g_xhi[MROWS*EMB];
__device__ u16 g_xlo[MROWS*EMB];
__device__ u16 g_ghi[MROWS*DD1];      // reused: vpack hi -> gate hi
__device__ u16 g_glo[MROWS*DD1];      // reused: vpack lo -> gate lo
__device__ u16 g_wthi[DD1*EMB];
__device__ u16 g_wtlo[DD1*EMB];
// RPE-private buffers (parallel stream)
__device__ u16 g_shi[SEQ*RDIM];
__device__ u16 g_slo[SEQ*RDIM];
__device__ u16 g_rwhi[DD1*RDIM];
__device__ u16 g_rwlo[DD1*RDIM];
// packed coefficient pairs
__device__ u32 g_pdhi[DD1*PD_LEN];
__device__ u32 g_pdlo[DD1*PD_LEN];

__device__ __forceinline__ u32 smem_u32(const void* p) {
    u32 a; asm("{ .reg .u64 t; cvta.to.shared.u64 t, %1; cvt.u32.u64 %0, t; }"
               : "=r"(a) : "l"(p));
    return a;
}

// ---------------- mma.sync / ldmatrix / cp.async ----------------
__device__ __forceinline__ void mma_bf16(float* c, const u32* a, const u32* b) {
    asm volatile("mma.sync.aligned.m16n8k16.row.col.f32.bf16.bf16.f32 "
        "{%0,%1,%2,%3}, {%4,%5,%6,%7}, {%8,%9}, {%0,%1,%2,%3};"
        : "+f"(c[0]), "+f"(c[1]), "+f"(c[2]), "+f"(c[3])
        : "r"(a[0]), "r"(a[1]), "r"(a[2]), "r"(a[3]), "r"(b[0]), "r"(b[1]));
}
__device__ __forceinline__ void ldsm4(u32* r, u32 addr) {
    asm volatile("ldmatrix.sync.aligned.m8n8.x4.shared.b16 {%0,%1,%2,%3}, [%4];"
        : "=r"(r[0]), "=r"(r[1]), "=r"(r[2]), "=r"(r[3]) : "r"(addr));
}
__device__ __forceinline__ void cp16(u32 saddr, const void* g) {
    asm volatile("cp.async.cg.shared.global [%0], [%1], 16;" :: "r"(saddr), "l"(g));
}
__device__ __forceinline__ void cp_commit() { asm volatile("cp.async.commit_group;" ::: "memory"); }
__device__ __forceinline__ void cp_wait1()  { asm volatile("cp.async.wait_group 1;" ::: "memory"); }

// ---------------- bf16 split helpers ----------------
__device__ __forceinline__ u16 bf_hi(float x) {
    __nv_bfloat16 b = __float2bfloat16(x);
    return *(u16*)&b;
}
__device__ __forceinline__ float bf_val(u16 b) {
    __nv_bfloat16 h = *(__nv_bfloat16*)&b;
    return __bfloat162float(h);
}

// ---------------- RPE init ----------------
__global__ void rpe_init_kernel(const float* __restrict__ Win,
                                const float* __restrict__ bin,
                                float* __restrict__ h) {
    int g = blockIdx.x * blockDim.x + threadIdx.x;
    if (g >= SEQ * RDIM) return;
    int n = g >> 9, r = g & 511;
    h[g] = (float)n * Win[r] + bin[r];
}

// --------- srms + relu rows of 512, emitting bf16 hi/lo split ---------
__global__ void srms_relu_split_kernel(const float* __restrict__ in,
                                       u16* __restrict__ hi, u16* __restrict__ lo) {
    int row = blockIdx.x;
    const float* p = in + (size_t)row * RDIM;
    int tid = threadIdx.x;
    float v0 = p[tid], v1 = p[tid + 256];
    float ss = v0 * v0 + v1 * v1;
    #pragma unroll
    for (int o = 16; o > 0; o >>= 1) ss += __shfl_xor_sync(0xffffffffu, ss, o);
    __shared__ float ws[8];
    if ((tid & 31) == 0) ws[tid >> 5] = ss;
    __syncthreads();
    float tot = 0.f;
    #pragma unroll
    for (int i = 0; i < 8; ++i) tot += ws[i];
    float scale = 1.f / (sqrtf(tot * (1.f / (float)RDIM)) + 1e-6f);
    float s0 = fmaxf(v0 * scale, 0.f), s1 = fmaxf(v1 * scale, 0.f);
    size_t o0 = (size_t)row * RDIM + tid;
    u16 h0 = bf_hi(s0), h1 = bf_hi(s1);
    hi[o0] = h0;        lo[o0] = bf_hi(s0 - bf_val(h0));
    hi[o0 + 256] = h1;  lo[o0 + 256] = bf_hi(s1 - bf_val(h1));
}

// ---- coeff decay + transpose ----
__global__ void coeff_scale_transpose(const float* __restrict__ coeffs,
                                      float* __restrict__ aT) {
    __shared__ float tile[32][33];
    int t0 = blockIdx.x << 5, c0 = blockIdx.y << 5;
    int tx = threadIdx.x, ty = threadIdx.y;   // (32,8)
    #pragma unroll
    for (int i = 0; i < 32; i += 8) {
        int t = t0 + ty + i;
        tile[ty + i][tx] = coeffs[(size_t)t * DD1 + c0 + tx] * powf(GAMMA_F, (float)t);
    }
    __syncthreads();
    #pragma unroll
    for (int i = 0; i < 32; i += 8)
        aT[(size_t)(c0 + ty + i) * SEQ + t0 + tx] = tile[tx][ty + i];
}

// ---- pack coefficient pairs ----
__global__ void coef_pack_kernel(const float* __restrict__ aT,
                                 u32* __restrict__ pdh, u32* __restrict__ pdl) {
    int g = blockIdx.x * blockDim.x + threadIdx.x;
    if (g >= DD1 * PD_LEN) return;
    int c = g / PD_LEN, slot = g - c * PD_LEN;
    int t = slot - 128;
    float a0 = (t >= 0 && t < SEQ) ? aT[(size_t)c * SEQ + t] : 0.f;
    float a1 = (t - 1 >= 0 && t - 1 < SEQ) ? aT[(size_t)c * SEQ + t - 1] : 0.f;
    u16 h0 = bf_hi(a0), h1 = bf_hi(a1);
    u16 l0 = bf_hi(a0 - bf_val(h0)), l1 = bf_hi(a1 - bf_val(h1));
    pdh[g] = ((u32)h1 << 16) | (u32)h0;
    pdl[g] = ((u32)l1 << 16) | (u32)l0;
}

// ---- vpack ----
__global__ void vpack_kernel(const float* __restrict__ v,
                             u32* __restrict__ ph, u32* __restrict__ pl) {
    __shared__ float tile[64][33];
    int b = blockIdx.z, n0 = blockIdx.x << 6, c0 = blockIdx.y << 5;
    int tx = threadIdx.x, ty = threadIdx.y;   // (32,16)
    for (int r = ty; r < 64; r += 16)
        tile[r][tx] = v[((size_t)(b * SEQ) + n0 + r) * DD1 + c0 + tx];
    __syncthreads();
    #pragma unroll
    for (int cc = 0; cc < 2; ++cc) {
        int cl = ty * 2 + cc;
        float x0 = tile[tx * 2][cl], x1 = tile[tx * 2 + 1][cl];
        u16 h0 = bf_hi(x0), h1 = bf_hi(x1);
        u16 l0 = bf_hi(x0 - bf_val(h0)), l1 = bf_hi(x1 - bf_val(h1));
        size_t o = (((size_t)(c0 + cl) * 8) + b) * 1024 + (n0 >> 1) + tx;
        ph[o] = ((u32)h1 << 16) | (u32)h0;
        pl[o] = ((u32)l1 << 16) | (u32)l0;
    }
}

// ---------------- Toeplitz-HMMA causal conv (6 MMA chains) ----------------
#define CV_SMEM (2*PD_LEN*4 + 2*8*1028*4 + 2048*9*4)   // 156928 B

__global__ __launch_bounds__(256, 1)
void convc_kernel(const u32* __restrict__ vph, const u32* __restrict__ vpl,
                  const u32* __restrict__ pdhi, const u32* __restrict__ pdlo,
                  float* __restrict__ convT)   // (B, D1, N)
{
    extern __shared__ char cs[];
    u32* pdh = (u32*)cs;
    u32* pdl = pdh + PD_LEN;
    u32* Vh  = pdl + PD_LEN;
    u32* Vl  = Vh + 8 * 1028;
    float* Osm = (float*)(Vl + 8 * 1028);

    const int c = blockIdx.x;
    const int tid = threadIdx.x, lane = tid & 31, wid = tid >> 5;
    const int lr = lane >> 2, q = lane & 3;
    const int mb = wid << 4;

    for (int k = tid; k < PD_LEN; k += 256) {
        pdh[k] = pdhi[(size_t)c * PD_LEN + k];
        pdl[k] = pdlo[(size_t)c * PD_LEN + k];
    }
    for (int k = tid; k < 8 * 1024; k += 256) {
        int b = k >> 10, sp = k & 1023;
        Vh[b * 1028 + sp] = vph[((size_t)c * 8 + b) * 1024 + sp];
        Vl[b * 1028 + sp] = vpl[((size_t)c * 8 + b) * 1024 + sp];
    }
    for (int k = tid; k < 2048 * 9; k += 256) Osm[k] = 0.f;
    __syncthreads();

    for (int d = 0; d < 16; ++d) {
        u32 Ah[8][4], Al[8][4];
        #pragma unroll
        for (int ks = 0; ks < 8; ++ks) {
            int s0 = 128 + (d << 7) + mb + lr - (ks << 4) - (q << 1);
            Ah[ks][0] = pdh[s0];     Ah[ks][1] = pdh[s0 + 8];
            Ah[ks][2] = pdh[s0 - 8]; Ah[ks][3] = Ah[ks][0];
            Al[ks][0] = pdl[s0];     Al[ks][1] = pdl[s0 + 8];
            Al[ks][2] = pdl[s0 - 8]; Al[ks][3] = Al[ks][0];
        }
        for (int i = d; i < 16; ++i) {
            const int j = i - d;
            float aH0[4] = {0,0,0,0}, aM0[4] = {0,0,0,0}, aL0[4] = {0,0,0,0};
            float aH1[4] = {0,0,0,0}, aM1[4] = {0,0,0,0}, aL1[4] = {0,0,0,0};
            const u32* vhb = &Vh[lr * 1028 + (j << 6) + q];
            const u32* vlb = &Vl[lr * 1028 + (j << 6) + q];
            #pragma unroll
            for (int ks = 0; ks < 4; ++ks) {
                u32 Bh0[2] = { vhb[ks << 3], vhb[(ks << 3) + 4] };
                u32 Bl0[2] = { vlb[ks << 3], vlb[(ks << 3) + 4] };
                int k2 = ks + 4;
                u32 Bh1[2] = { vhb[k2 << 3], vhb[(k2 << 3) + 4] };
                u32 Bl1[2] = { vlb[k2 << 3], vlb[(k2 << 3) + 4] };
                mma_bf16(aH0, Ah[ks], Bh0);
                mma_bf16(aH1, Ah[k2], Bh1);
                mma_bf16(aM0, Ah[ks], Bl0);
                mma_bf16(aM1, Ah[k2], Bl1);
                mma_bf16(aL0, Al[ks], Bh0);
                mma_bf16(aL1, Al[k2], Bh1);
            }
            float* orow = &Osm[((i << 7) + mb + lr) * 9 + (q << 1)];
            orow[0]      += (aH0[0]+aH1[0]) + (aM0[0]+aM1[0]) + (aL0[0]+aL1[0]);
            orow[1]      += (aH0[1]+aH1[1]) + (aM0[1]+aM1[1]) + (aL0[1]+aL1[1]);
            orow[8*9]    += (aH0[2]+aH1[2]) + (aM0[2]+aM1[2]) + (aL0[2]+aL1[2]);
            orow[8*9+1]  += (aH0[3]+aH1[3]) + (aM0[3]+aM1[3]) + (aL0[3]+aL1[3]);
        }
    }
    __syncthreads();
    for (int k = tid; k < 2048 * 8; k += 256) {
        int b = k >> 11, n = k & 2047;
        convT[((size_t)(b * DD1 + c)) * SEQ + n] = Osm[n * 9 + b];
    }
}

// ---- fused gate + split with transposed conv read ----
__global__ void gate_split_t_kernel(const float* __restrict__ u,
                                    const float* __restrict__ convT,
                                    u16* __restrict__ hi, u16* __restrict__ lo) {
    __shared__ float tile[32][33];
    int b = blockIdx.z, c0 = blockIdx.x << 5, n0 = blockIdx.y << 5;
    int tx = threadIdx.x, ty = threadIdx.y;   // (32,8)
    #pragma unroll
    for (int i = 0; i < 32; i += 8)
        tile[ty + i][tx] = convT[((size_t)(b * DD1 + c0 + ty + i)) * SEQ + n0 + tx];
    __syncthreads();
    #pragma unroll
    for (int i = 0; i < 32; i += 8) {
        size_t off = ((size_t)(b * SEQ + n0 + ty + i)) * DD1 + c0 + tx;
        float g = u[off] * tile[tx][ty + i];
        u16 h = bf_hi(g);
        hi[off] = h;
        lo[off] = bf_hi(g - bf_val(h));
    }
}

// ---------------- element split kernels ----------------
__global__ void split_kernel(const float* __restrict__ x, u16* __restrict__ hi,
                             u16* __restrict__ lo, int n) {
    int g = (blockIdx.x * blockDim.x + threadIdx.x) << 2;
    if (g >= n) return;
    float4 v = *(const float4*)(x + g);
    u16 h[4], l[4];
    float vv[4] = { v.x, v.y, v.z, v.w };
    #pragma unroll
    for (int i = 0; i < 4; ++i) {
        h[i] = bf_hi(vv[i]);
        l[i] = bf_hi(vv[i] - bf_val(h[i]));
    }
    *(uint2*)&hi[g] = *(uint2*)h;
    *(uint2*)&lo[g] = *(uint2*)l;
}
__global__ void wsplit_t_kernel(const float* __restrict__ W, u16* __restrict__ hi,
                                u16* __restrict__ lo, int K, int N) {
    __shared__ float tile[32][33];
    int n0 = blockIdx.x << 5, k0 = blockIdx.y << 5;
    int tx = threadIdx.x, ty = threadIdx.y;   // (32,8)
    #pragma unroll
    for (int i = 0; i < 32; i += 8)
        tile[ty + i][tx] = W[(size_t)(k0 + ty + i) * N + n0 + tx];
    __syncthreads();
    #pragma unroll
    for (int i = 0; i < 32; i += 8) {
        float v = tile[tx][ty + i];
        size_t o = (size_t)(n0 + ty + i) * K + k0 + tx;
        u16 h = bf_hi(v);
        hi[o] = h;
        lo[o] = bf_hi(v - bf_val(h));
    }
}

// ---------------- HMMA split-GEMM v2: 512 threads, 3-stage pipeline ----------------
#define PITCH   72
#define TILE_B  (128*PITCH*2)           // 18432 B
#define STAGE_B (4*TILE_B)              // 73728 B
#define MM_SMEM (3*STAGE_B)             // 221184 B

// thread t: r = t>>2 (0..127), hh = t&3 -> copies 32B (elems hh*16..hh*16+15)
// of row r in each of 4 tiles.
__device__ __forceinline__ void fill_stage(u32 st,
        const u16* __restrict__ Ah, const u16* __restrict__ Al,
        const u16* __restrict__ Bh, const u16* __restrict__ Bl,
        int row0, int col0, int K, int kc, int t) {
    const int r = t >> 2, hh = t & 3;
    const u32 so = (u32)(r * PITCH + hh * 16) * 2;
    const size_t goA = (size_t)(row0 + r) * K + (kc << 6) + hh * 16;
    const size_t goB = (size_t)(col0 + r) * K + (kc << 6) + hh * 16;
    #pragma unroll
    for (int e = 0; e < 2; ++e) {
        cp16(st + so + e*16,              Ah + goA + e*8);
        cp16(st + TILE_B + so + e*16,     Al + goA + e*8);
        cp16(st + 2*TILE_B + so + e*16,   Bh + goB + e*8);
        cp16(st + 3*TILE_B + so + e*16,   Bl + goB + e*8);
    }
}

template<int ACT>
__global__ __launch_bounds__(512, 1)
void gemm_mma_kernel(const u16* __restrict__ Ah, const u16* __restrict__ Al,
                     const u16* __restrict__ Bh, const u16* __restrict__ Bl,
                     const float* __restrict__ bias, float* __restrict__ C,
                     int M, int N, int K)
{
    extern __shared__ char dsm[];
    const u32 sb = smem_u32(dsm);
    const int tid = threadIdx.x, lane = tid & 31, wid = tid >> 5;
    const int wm = wid & 3;            // 0..3 -> 32-row block
    const int wn = wid >> 2;           // 0..3 -> 32-col block
    const int row0 = blockIdx.y * 128, col0 = blockIdx.x * 128;
    const int nkc = K >> 6;

    const int q = lane >> 3, l7 = lane & 7;
    u32 aoff[2], boff[2];
    #pragma unroll
    for (int i = 0; i < 2; ++i)
        aoff[i] = (u32)((wm*32 + i*16 + (q & 1)*8 + l7) * PITCH + (q >> 1)*8) * 2;
    #pragma unroll
    for (int jj = 0; jj < 2; ++jj)
        boff[jj] = (u32)((wn*32 + jj*16 + (q >> 1)*8 + l7) * PITCH + (q & 1)*8) * 2;

    float acc[2][4][4];
    #pragma unroll
    for (int i = 0; i < 2; ++i)
        #pragma unroll
        for (int j = 0; j < 4; ++j)
            #pragma unroll
            for (int r = 0; r < 4; ++r) acc[i][j][r] = 0.f;

    fill_stage(sb, Ah, Al, Bh, Bl, row0, col0, K, 0, tid);
    cp_commit();
    if (nkc > 1) fill_stage(sb + STAGE_B, Ah, Al, Bh, Bl, row0, col0, K, 1, tid);
    cp_commit();

    int stg = 0;
    for (int kc = 0; kc < nkc; ++kc) {
        cp_wait1();
        __syncthreads();
        const u32 st = sb + stg * STAGE_B;
        int nstg = stg + 2; if (nstg >= 3) nstg -= 3;
        if (kc + 2 < nkc)
            fill_stage(sb + nstg * STAGE_B, Ah, Al, Bh, Bl, row0, col0, K, kc + 2, tid);
        cp_commit();

        #pragma unroll
        for (int ks = 0; ks < 4; ++ks) {
            u32 ah[2][4], al[2][4], bh[2][4], bl[2][4];
            #pragma unroll
            for (int i = 0; i < 2; ++i) {
                ldsm4(ah[i], st + aoff[i] + ks*32);
                ldsm4(al[i], st + TILE_B + aoff[i] + ks*32);
            }
            #pragma unroll
            for (int jj = 0; jj < 2; ++jj) {
                ldsm4(bh[jj], st + 2*TILE_B + boff[jj] + ks*32);
                ldsm4(bl[jj], st + 3*TILE_B + boff[jj] + ks*32);
            }
            #pragma unroll
            for (int i = 0; i < 2; ++i)
                #pragma unroll
                for (int jn = 0; jn < 4; ++jn)
                    mma_bf16(acc[i][jn], ah[i], &bh[jn >> 1][(jn & 1) * 2]);
            #pragma unroll
            for (int i = 0; i < 2; ++i)
                #pragma unroll
                for (int jn = 0; jn < 4; ++jn)
                    mma_bf16(acc[i][jn], ah[i], &bl[jn >> 1][(jn & 1) * 2]);
            #pragma unroll
            for (int i = 0; i < 2; ++i)
                #pragma unroll
                for (int jn = 0; jn < 4; ++jn)
                    mma_bf16(acc[i][jn], al[i], &bh[jn >> 1][(jn & 1) * 2]);
        }
        if (++stg == 3) stg = 0;
    }

    const int mrow = lane >> 2, ncol = (lane & 3) * 2;
    #pragma unroll
    for (int i = 0; i < 2; ++i) {
        const int m = row0 + wm*32 + i*16 + mrow;
        #pragma unroll
        for (int jn = 0; jn < 4; ++jn) {
            const int n = col0 + wn*32 + jn*8 + ncol;
            const float b0 = bias[n], b1 = bias[n + 1];
            float c0 = acc[i][jn][0] + b0, c1 = acc[i][jn][1] + b1;
            float c2 = acc[i][jn][2] + b0, c3 = acc[i][jn][3] + b1;
            if (ACT) {
                c0 = c0/(1.f+__expf(-c0)); c1 = c1/(1.f+__expf(-c1));
                c2 = c2/(1.f+__expf(-c2)); c3 = c3/(1.f+__expf(-c3));
            }
            *(float2*)&C[(size_t)m * N + n]       = make_float2(c0, c1);
            *(float2*)&C[(size_t)(m + 8) * N + n] = make_float2(c2, c3);
        }
    }
}

// ================================================================
extern "C" void kernel_launch(void* const* d_in, const int* in_sizes, int n_in,
                              void* d_out, int out_size) {
    const float* x     = (const float*)d_in[0];
    const float* Wu    = (const float*)d_in[1];
    const float* bu    = (const float*)d_in[2];
    const float* Wv    = (const float*)d_in[3];
    const float* bv    = (const float*)d_in[4];
    const float* Wo    = (const float*)d_in[5];
    const float* bo    = (const float*)d_in[6];
    const float* rWin  = (const float*)d_in[7];
    const float* rbin  = (const float*)d_in[8];
    const float* rW    = (const float*)d_in[9];
    const float* rb    = (const float*)d_in[10];
    const float* rWout = (const float*)d_in[11];
    const float* rbout = (const float*)d_in[12];
    float* out = (float*)d_out;

    float *u, *v, *cvT, *h, *cf, *aT;
    u16 *xhi, *xlo, *ghi, *glo, *wthi, *wtlo, *shi, *slo, *rwhi, *rwlo;
    u32 *pdh, *pdl;
    cudaGetSymbolAddress((void**)&u,  g_u);
    cudaGetSymbolAddress((void**)&v,  g_vbuf);
    cudaGetSymbolAddress((void**)&cvT, g_vT);
    cudaGetSymbolAddress((void**)&h,  g_h);
    cudaGetSymbolAddress((void**)&cf, g_coeffs);
    cudaGetSymbolAddress((void**)&aT, g_acoefT);
    cudaGetSymbolAddress((void**)&xhi, g_xhi);
    cudaGetSymbolAddress((void**)&xlo, g_xlo);
    cudaGetSymbolAddress((void**)&ghi, g_ghi);
    cudaGetSymbolAddress((void**)&glo, g_glo);
    cudaGetSymbolAddress((void**)&wthi, g_wthi);
    cudaGetSymbolAddress((void**)&wtlo, g_wtlo);
    cudaGetSymbolAddress((void**)&shi, g_shi);
    cudaGetSymbolAddress((void**)&slo, g_slo);
    cudaGetSymbolAddress((void**)&rwhi, g_rwhi);
    cudaGetSymbolAddress((void**)&rwlo, g_rwlo);
    cudaGetSymbolAddress((void**)&pdh, g_pdhi);
    cudaGetSymbolAddress((void**)&pdl, g_pdlo);
    u32* vph = (u32*)ghi;
    u32* vpl = (u32*)glo;

    cudaFuncSetAttribute(gemm_mma_kernel<0>, cudaFuncAttributeMaxDynamicSharedMemorySize, MM_SMEM);
    cudaFuncSetAttribute(gemm_mma_kernel<1>, cudaFuncAttributeMaxDynamicSharedMemorySize, MM_SMEM);
    cudaFuncSetAttribute(convc_kernel, cudaFuncAttributeMaxDynamicSharedMemorySize, CV_SMEM);

    // ---- fork a side stream for the RPE chain ----
    cudaStream_t s2;
    cudaStreamCreate(&s2);
    cudaEvent_t eFork, eJoin;
    cudaEventCreateWithFlags(&eFork, cudaEventDisableTiming);
    cudaEventCreateWithFlags(&eJoin, cudaEventDisableTiming);
    cudaEventRecord(eFork, 0);
    cudaStreamWaitEvent(s2, eFork, 0);

    // ==== RPE chain on s2 ====
    rpe_init_kernel<<<(SEQ * RDIM + 255) / 256, 256, 0, s2>>>(rWin, rbin, h);
    for (int i = 0; i < 3; ++i) {
        srms_relu_split_kernel<<<SEQ, 256, 0, s2>>>(h, shi, slo);
        wsplit_t_kernel<<<dim3(RDIM / 32, RDIM / 32), dim3(32, 8), 0, s2>>>(
            rW + (size_t)i * RDIM * RDIM, rwhi, rwlo, RDIM, RDIM);
        gemm_mma_kernel<0><<<dim3(RDIM / 128, SEQ / 128), 512, MM_SMEM, s2>>>(
            shi, slo, rwhi, rwlo, rb + i * RDIM, h, SEQ, RDIM, RDIM);
    }
    srms_relu_split_kernel<<<SEQ, 256, 0, s2>>>(h, shi, slo);
    wsplit_t_kernel<<<dim3(DD1 / 32, RDIM / 32), dim3(32, 8), 0, s2>>>(
        rWout, rwhi, rwlo, RDIM, DD1);
    gemm_mma_kernel<0><<<dim3(DD1 / 128, SEQ / 128), 512, MM_SMEM, s2>>>(
        shi, slo, rwhi, rwlo, rbout, cf, SEQ, DD1, RDIM);
    coeff_scale_transpose<<<dim3(SEQ / 32, DD1 / 32), dim3(32, 8), 0, s2>>>(cf, aT);
    coef_pack_kernel<<<(DD1 * PD_LEN + 255) / 256, 256, 0, s2>>>(aT, pdh, pdl);
    cudaEventRecord(eJoin, s2);

    // ==== main stream: x split, u/v GEMMs, vpack ====
    split_kernel<<<(MROWS * EMB / 4 + 255) / 256, 256>>>(x, xhi, xlo, MROWS * EMB);

    wsplit_t_kernel<<<dim3(DD1 / 32, EMB / 32), dim3(32, 8)>>>(Wu, wthi, wtlo, EMB, DD1);
    gemm_mma_kernel<1><<<dim3(DD1 / 128, MROWS / 128), 512, MM_SMEM>>>(
        xhi, xlo, wthi, wtlo, bu, u, MROWS, DD1, EMB);

    wsplit_t_kernel<<<dim3(DD1 / 32, EMB / 32), dim3(32, 8)>>>(Wv, wthi, wtlo, EMB, DD1);
    gemm_mma_kernel<1><<<dim3(DD1 / 128, MROWS / 128), 512, MM_SMEM>>>(
        xhi, xlo, wthi, wtlo, bv, v, MROWS, DD1, EMB);

    vpack_kernel<<<dim3(SEQ / 64, DD1 / 32, BATCH), dim3(32, 16)>>>(v, vph, vpl);

    // ---- join: convc needs both vpack (main) and coef_pack (s2) ----
    cudaStreamWaitEvent(0, eJoin, 0);
    convc_kernel<<<DD1, 256, CV_SMEM>>>(vph, vpl, pdh, pdl, cvT);

    // ---- fused gate + split ----
    gate_split_t_kernel<<<dim3(DD1 / 32, SEQ / 32, BATCH), dim3(32, 8)>>>(u, cvT, ghi, glo);

    // ---- out = g @ Wo + bo ----
    wsplit_t_kernel<<<dim3(EMB / 32, DD1 / 32), dim3(32, 8)>>>(Wo, wthi, wtlo, DD1, EMB);
    gemm_mma_kernel<0><<<dim3(EMB / 128, MROWS / 128), 512, MM_SMEM>>>(
        ghi, glo, wthi, wtlo, bo, out, MROWS, EMB, DD1);
}